// round 4
// baseline (speedup 1.0000x reference)
#include <cuda_runtime.h>

#define RES_   0.16f
#define XMIN_ (-51.2f)
#define YMIN_ (-51.2f)
#define EPS_   1e-5f
#define NEG_  (-1000000000.0f)

// Folded-parameter scratch (device globals: allocation-free).
__device__ float d_A[8 * 64];
__device__ float d_W2f[64 * 64];
__device__ float d_t2f[64];
__device__ int   d_i64flag;   // 1 -> integer inputs are int64, 0 -> int32

// ---- packed fp32x2 helpers (Blackwell FFMA2 path) ----
__device__ __forceinline__ unsigned long long pk2(float lo, float hi) {
    unsigned long long r;
    asm("mov.b64 %0, {%1, %2};" : "=l"(r) : "f"(lo), "f"(hi));
    return r;
}
__device__ __forceinline__ void upk2(unsigned long long v, float& lo, float& hi) {
    asm("mov.b64 {%0, %1}, %2;" : "=f"(lo), "=f"(hi) : "l"(v));
}
__device__ __forceinline__ unsigned long long ffma2(unsigned long long a,
                                                    unsigned long long b,
                                                    unsigned long long c) {
    unsigned long long d;
    asm("fma.rn.f32x2 %0, %1, %2, %3;" : "=l"(d) : "l"(a), "l"(b), "l"(c));
    return d;
}
__device__ __forceinline__ unsigned long long fadd2(unsigned long long a,
                                                    unsigned long long b) {
    unsigned long long d;
    asm("add.rn.f32x2 %0, %1, %2;" : "=l"(d) : "l"(a), "l"(b));
    return d;
}

// Detect whether the integer inputs are int64 or int32 (odd words all zero -> i64).
__global__ void pfn_detect(const int* __restrict__ npts_i32, int nwords) {
    int f = 1;
    #pragma unroll 1
    for (int i = 1; i < nwords; i += 2) {
        if (npts_i32[i] != 0) { f = 0; break; }
    }
    d_i64flag = f;
}

__global__ void pfn_prep(const float* __restrict__ W1, const float* __restrict__ b1,
                         const float* __restrict__ g1, const float* __restrict__ beta1,
                         const float* __restrict__ m1, const float* __restrict__ v1,
                         const float* __restrict__ W2, const float* __restrict__ b2,
                         const float* __restrict__ g2, const float* __restrict__ beta2,
                         const float* __restrict__ m2, const float* __restrict__ v2) {
    int c = threadIdx.x;  // 0..63
    float s1 = g1[c] * rsqrtf(v1[c] + EPS_);
    float w0 = W1[0 * 64 + c], w1 = W1[1 * 64 + c], w2 = W1[2 * 64 + c];
    float w3 = W1[3 * 64 + c], w4 = W1[4 * 64 + c], w5 = W1[5 * 64 + c];
    float w6 = W1[6 * 64 + c], w7 = W1[7 * 64 + c], w8 = W1[8 * 64 + c];
    d_A[0 * 64 + c] = (w0 + w4 + w7) * s1;   // x
    d_A[1 * 64 + c] = (w1 + w5 + w8) * s1;   // y
    d_A[2 * 64 + c] = (w2 + w6) * s1;        // z
    d_A[3 * 64 + c] = w3 * s1;               // r
    d_A[4 * 64 + c] = (w4 + w7) * s1;        // xc coeff
    d_A[5 * 64 + c] = (w5 + w8) * s1;        // yc coeff
    d_A[6 * 64 + c] = w6 * s1;               // z_mean coeff
    d_A[7 * 64 + c] = (b1[c] - m1[c]) * s1 + beta1[c];

    float s2 = g2[c] * rsqrtf(v2[c] + EPS_);
    for (int k = 0; k < 64; k++) d_W2f[k * 64 + c] = W2[k * 64 + c] * s2;
    d_t2f[c] = (b2[c] - m2[c]) * s2 + beta2[c];
}

// One warp per pillar. Lane owns channels (lane, lane+32).
// Layer-2 uses packed fp32x2 FMA: weights pre-packed (w[c0],w[c1]) in 64-bit regs,
// h1 stored DUPLICATED in smem so LDS.128 yields two ready (h,h) multiplier pairs.
__global__ __launch_bounds__(128) void pfn_main(
    const float4* __restrict__ pillars,   // [P*32] float4 (x,y,z,r)
    const void*  __restrict__ coords_raw, // [P*2] int32 or int64 (row, col)
    const void*  __restrict__ npts_raw,   // [P]   int32 or int64
    float* __restrict__ out, int P)
{
    const int warp = threadIdx.x >> 5;
    const int lane = threadIdx.x & 31;
    const int p = blockIdx.x * 4 + warp;

    // per-warp duplicated h1: 64 channels x (h,h) = 128 floats, 16B-aligned
    __shared__ __align__(16) float hdup[4][128];

    if (p >= P) return;

    const int i64 = d_i64flag;

    int npts;
    float crow, ccol;
    if (i64) {
        npts = (int)((const long long*)npts_raw)[p];
        crow = (float)((const long long*)coords_raw)[p * 2 + 0];
        ccol = (float)((const long long*)coords_raw)[p * 2 + 1];
    } else {
        npts = ((const int*)npts_raw)[p];
        crow = (float)((const int*)coords_raw)[p * 2 + 0];
        ccol = (float)((const int*)coords_raw)[p * 2 + 1];
    }
    npts = min(max(npts, 0), 32);   // structural hang guard

    const float4 pt = pillars[p * 32 + lane];

    float zs = (lane < npts) ? pt.z : 0.0f;
    #pragma unroll
    for (int o = 16; o; o >>= 1) zs += __shfl_xor_sync(0xFFFFFFFFu, zs, o);
    const float zm = zs / fmaxf((float)npts, 1.0f);

    const float xc = (ccol + 0.5f) * RES_ + XMIN_;
    const float yc = (crow + 0.5f) * RES_ + YMIN_;

    const int c0 = lane, c1 = lane + 32;

    const float ax0 = d_A[0 * 64 + c0], ay0 = d_A[1 * 64 + c0];
    const float az0 = d_A[2 * 64 + c0], ar0 = d_A[3 * 64 + c0];
    const float ax1 = d_A[0 * 64 + c1], ay1 = d_A[1 * 64 + c1];
    const float az1 = d_A[2 * 64 + c1], ar1 = d_A[3 * 64 + c1];
    const float bias0 = d_A[7 * 64 + c0] - xc * d_A[4 * 64 + c0]
                      - yc * d_A[5 * 64 + c0] - zm * d_A[6 * 64 + c0];
    const float bias1 = d_A[7 * 64 + c1] - xc * d_A[4 * 64 + c1]
                      - yc * d_A[5 * 64 + c1] - zm * d_A[6 * 64 + c1];

    // W2 column pairs packed into 64-bit registers: (w[k][c0], w[k][c1]).
    unsigned long long wp[64];
    #pragma unroll
    for (int k = 0; k < 64; k++) {
        wp[k] = pk2(d_W2f[k * 64 + c0], d_W2f[k * 64 + c1]);
    }
    const float t20 = d_t2f[c0], t21 = d_t2f[c1];

    float acc0 = NEG_, acc1 = NEG_;
    float2* hp2 = (float2*)hdup[warp];                        // [64] (h,h) pairs
    const ulonglong2* hp128 = (const ulonglong2*)hdup[warp];  // [32] pairs-of-pairs

    for (int j = 0; j < npts; j++) {
        const float x  = __shfl_sync(0xFFFFFFFFu, pt.x, j);
        const float y  = __shfl_sync(0xFFFFFFFFu, pt.y, j);
        const float zz = __shfl_sync(0xFFFFFFFFu, pt.z, j);
        const float r  = __shfl_sync(0xFFFFFFFFu, pt.w, j);

        // Layer 1 (folded BN + rank-4 collapse) + ReLU.
        float h0 = fmaf(ax0, x, fmaf(ay0, y, fmaf(az0, zz, fmaf(ar0, r, bias0))));
        float h1 = fmaf(ax1, x, fmaf(ay1, y, fmaf(az1, zz, fmaf(ar1, r, bias1))));
        h0 = fmaxf(h0, 0.0f);
        h1 = fmaxf(h1, 0.0f);

        __syncwarp();                    // previous iteration's reads done
        hp2[c0] = make_float2(h0, h0);   // STS.64, duplicated
        hp2[c1] = make_float2(h1, h1);
        __syncwarp();                    // stores visible

        // Layer 2: 64 packed FMAs (2 channels per instruction), 2 acc chains.
        unsigned long long accA = 0ull, accB = 0ull;
        #pragma unroll
        for (int k = 0; k < 32; k++) {
            const ulonglong2 hv = hp128[k];   // (h_{2k},h_{2k}) , (h_{2k+1},h_{2k+1})
            accA = ffma2(hv.x, wp[2 * k + 0], accA);
            accB = ffma2(hv.y, wp[2 * k + 1], accB);
        }
        const unsigned long long s = fadd2(accA, accB);
        float s0, s1;
        upk2(s, s0, s1);
        acc0 = fmaxf(acc0, fmaxf(t20 + s0, 0.0f));
        acc1 = fmaxf(acc1, fmaxf(t21 + s1, 0.0f));
    }

    out[p * 64 + c0] = acc0;
    out[p * 64 + c1] = acc1;
}

extern "C" void kernel_launch(void* const* d_in, const int* in_sizes, int n_in,
                              void* d_out, int out_size) {
    const float* pillars = (const float*)d_in[0];   // (P,32,4) f32
    const void*  coords  = d_in[1];                 // (P,2) int32 or int64
    const void*  npts    = d_in[2];                 // (P,)  int32 or int64
    const float* W1    = (const float*)d_in[3];
    const float* b1    = (const float*)d_in[4];
    const float* g1    = (const float*)d_in[5];
    const float* beta1 = (const float*)d_in[6];
    const float* m1    = (const float*)d_in[7];
    const float* v1    = (const float*)d_in[8];
    const float* W2    = (const float*)d_in[9];
    const float* b2    = (const float*)d_in[10];
    const float* g2    = (const float*)d_in[11];
    const float* beta2 = (const float*)d_in[12];
    const float* m2    = (const float*)d_in[13];
    const float* v2    = (const float*)d_in[14];

    const int P = in_sizes[2];

    const int nwords = (P >= 64) ? 129 : (2 * P);
    pfn_detect<<<1, 1>>>((const int*)npts, nwords);
    pfn_prep<<<1, 64>>>(W1, b1, g1, beta1, m1, v1, W2, b2, g2, beta2, m2, v2);

    const int warpsPerBlock = 4;
    const int blocks = (P + warpsPerBlock - 1) / warpsPerBlock;
    pfn_main<<<blocks, warpsPerBlock * 32>>>(
        (const float4*)pillars, coords, npts, (float*)d_out, P);
}

// round 8
// speedup vs baseline: 2.9233x; 2.9233x over previous
#include <cuda_runtime.h>
#include <cuda_bf16.h>
#include <cstdint>

#define RES_   0.16f
#define XMIN_ (-51.2f)
#define YMIN_ (-51.2f)
#define EPS_   1e-5f
#define NEG_  (-1000000000.0f)

// Folded params (device globals: allocation-free).
__device__ float d_A[8 * 64];
__device__ float d_t2f[64];
__device__ __align__(16) __nv_bfloat16 d_Bhi[64 * 64];  // [n][k] = bf16_hi(W2f[k][n])
__device__ __align__(16) __nv_bfloat16 d_Blo[64 * 64];  // [n][k] = bf16_lo(W2f[k][n])
__device__ int d_i64flag;

__device__ __forceinline__ uint32_t smem_u32(const void* p) {
    uint32_t a;
    asm("{ .reg .u64 t; cvta.to.shared.u64 t, %1; cvt.u32.u64 %0, t; }" : "=r"(a) : "l"(p));
    return a;
}
__device__ __forceinline__ void ldsm4(uint32_t a, uint32_t& r0, uint32_t& r1,
                                      uint32_t& r2, uint32_t& r3) {
    asm volatile("ldmatrix.sync.aligned.m8n8.x4.shared.b16 {%0,%1,%2,%3}, [%4];"
                 : "=r"(r0), "=r"(r1), "=r"(r2), "=r"(r3) : "r"(a));
}
__device__ __forceinline__ void mma16816(float* d, uint32_t a0, uint32_t a1,
                                         uint32_t a2, uint32_t a3,
                                         uint32_t b0, uint32_t b1) {
    asm volatile(
        "mma.sync.aligned.m16n8k16.row.col.f32.bf16.bf16.f32 "
        "{%0,%1,%2,%3}, {%4,%5,%6,%7}, {%8,%9}, {%0,%1,%2,%3};"
        : "+f"(d[0]), "+f"(d[1]), "+f"(d[2]), "+f"(d[3])
        : "r"(a0), "r"(a1), "r"(a2), "r"(a3), "r"(b0), "r"(b1));
}

__global__ void pfn_detect(const int* __restrict__ npts_i32, int nwords) {
    int f = 1;
    #pragma unroll 1
    for (int i = 1; i < nwords; i += 2) {
        if (npts_i32[i] != 0) { f = 0; break; }
    }
    d_i64flag = f;
}

__global__ void pfn_prep(const float* __restrict__ W1, const float* __restrict__ b1,
                         const float* __restrict__ g1, const float* __restrict__ beta1,
                         const float* __restrict__ m1, const float* __restrict__ v1,
                         const float* __restrict__ W2, const float* __restrict__ b2,
                         const float* __restrict__ g2, const float* __restrict__ beta2,
                         const float* __restrict__ m2, const float* __restrict__ v2) {
    int c = threadIdx.x;  // 0..63
    float s1 = g1[c] * rsqrtf(v1[c] + EPS_);
    float w0 = W1[0*64+c], w1 = W1[1*64+c], w2 = W1[2*64+c];
    float w3 = W1[3*64+c], w4 = W1[4*64+c], w5 = W1[5*64+c];
    float w6 = W1[6*64+c], w7 = W1[7*64+c], w8 = W1[8*64+c];
    d_A[0*64+c] = (w0 + w4 + w7) * s1;
    d_A[1*64+c] = (w1 + w5 + w8) * s1;
    d_A[2*64+c] = (w2 + w6) * s1;
    d_A[3*64+c] = w3 * s1;
    d_A[4*64+c] = (w4 + w7) * s1;
    d_A[5*64+c] = (w5 + w8) * s1;
    d_A[6*64+c] = w6 * s1;
    d_A[7*64+c] = (b1[c] - m1[c]) * s1 + beta1[c];

    float s2 = g2[c] * rsqrtf(v2[c] + EPS_);
    for (int k = 0; k < 64; k++) {
        float w = W2[k*64 + c] * s2;                  // W2f[k][c]
        __nv_bfloat16 hb = __float2bfloat16(w);
        float rem = w - __bfloat162float(hb);
        d_Bhi[c*64 + k] = hb;                         // [n=c][k]
        d_Blo[c*64 + k] = __float2bfloat16(rem);
    }
    d_t2f[c] = (b2[c] - m2[c]) * s2 + beta2[c];
}

// ---------------- main kernel: 1 warp = 1 pillar, 4 pillars/CTA ----------------
// Dynamic SMEM layout (144B row stride = 128B data + 16B pad, 16B aligned):
//   A_hi : 4 warps x 32 rows x 144B = 18432
//   A_lo : 18432
//   B_hi : 64 rows x 144B          =  9216
//   B_lo :  9216
#define ROWB     144
#define OF_AH    0
#define OF_AL    18432
#define OF_BH    36864
#define OF_BL    46080
#define SMEM_TOT 55296

__global__ void __launch_bounds__(128) pfn_mma(
    const float4* __restrict__ pillars,
    const void*  __restrict__ coords_raw,
    const void*  __restrict__ npts_raw,
    float* __restrict__ out, int P)
{
    extern __shared__ __align__(128) unsigned char smem[];
    const int tid  = threadIdx.x;
    const int wid  = tid >> 5;
    const int lane = tid & 31;

    // ---- B tiles -> smem (shared by all 4 warps) ----
    {
        const uint4* gh = (const uint4*)d_Bhi;   // 64 rows x 8 uint4
        const uint4* gl = (const uint4*)d_Blo;
        #pragma unroll
        for (int g = tid; g < 512; g += 128) {
            const int row = g >> 3, c = g & 7;
            *(uint4*)(smem + OF_BH + row*ROWB + c*16) = gh[g];
            *(uint4*)(smem + OF_BL + row*ROWB + c*16) = gl[g];
        }
    }
    __syncthreads();   // only block-wide sync; warps independent afterwards

    const int  p  = blockIdx.x * 4 + wid;
    const bool pv = (p < P);
    const int  pe = pv ? p : 0;

    int npts; float crow, ccol;
    if (d_i64flag) {
        npts = (int)((const long long*)npts_raw)[pe];
        crow = (float)((const long long*)coords_raw)[pe*2 + 0];
        ccol = (float)((const long long*)coords_raw)[pe*2 + 1];
    } else {
        npts = ((const int*)npts_raw)[pe];
        crow = (float)((const int*)coords_raw)[pe*2 + 0];
        ccol = (float)((const int*)coords_raw)[pe*2 + 1];
    }
    npts = min(max(npts, 0), 32);
    if (!pv) return;

    if (npts == 0) {            // empty pillar -> exactly NEG everywhere
        out[p*64 + lane]      = NEG_;
        out[p*64 + lane + 32] = NEG_;
        return;
    }

    // ---- layer 1: folded BN + rank-4 collapse; bf16 hi/lo into A tiles ----
    const float4 pt = pillars[pe * 32 + lane];
    float zs = (lane < npts) ? pt.z : 0.0f;
    #pragma unroll
    for (int o = 16; o; o >>= 1) zs += __shfl_xor_sync(0xFFFFFFFFu, zs, o);
    const float zm = zs / fmaxf((float)npts, 1.0f);

    const float xc = (ccol + 0.5f) * RES_ + XMIN_;
    const float yc = (crow + 0.5f) * RES_ + YMIN_;

    const int c0 = lane, c1 = lane + 32;
    const float ax0 = d_A[0*64+c0], ay0 = d_A[1*64+c0], az0 = d_A[2*64+c0], ar0 = d_A[3*64+c0];
    const float ax1 = d_A[0*64+c1], ay1 = d_A[1*64+c1], az1 = d_A[2*64+c1], ar1 = d_A[3*64+c1];
    const float bias0 = d_A[7*64+c0] - xc*d_A[4*64+c0] - yc*d_A[5*64+c0] - zm*d_A[6*64+c0];
    const float bias1 = d_A[7*64+c1] - xc*d_A[4*64+c1] - yc*d_A[5*64+c1] - zm*d_A[6*64+c1];

    __nv_bfloat16* ah = (__nv_bfloat16*)(smem + OF_AH + wid * 32 * ROWB);
    __nv_bfloat16* al = (__nv_bfloat16*)(smem + OF_AL + wid * 32 * ROWB);
    const int rw = ROWB / 2;   // u16 per row (72)

    for (int j = 0; j < npts; j++) {
        const float x  = __shfl_sync(0xFFFFFFFFu, pt.x, j);
        const float y  = __shfl_sync(0xFFFFFFFFu, pt.y, j);
        const float zz = __shfl_sync(0xFFFFFFFFu, pt.z, j);
        const float r  = __shfl_sync(0xFFFFFFFFu, pt.w, j);

        float h0 = fmaf(ax0, x, fmaf(ay0, y, fmaf(az0, zz, fmaf(ar0, r, bias0))));
        float h1 = fmaf(ax1, x, fmaf(ay1, y, fmaf(az1, zz, fmaf(ar1, r, bias1))));
        h0 = fmaxf(h0, 0.0f);
        h1 = fmaxf(h1, 0.0f);

        const __nv_bfloat16 b0 = __float2bfloat16(h0);
        const __nv_bfloat16 b1v = __float2bfloat16(h1);
        ah[j*rw + c0] = b0;
        ah[j*rw + c1] = b1v;
        al[j*rw + c0] = __float2bfloat16(h0 - __bfloat162float(b0));
        al[j*rw + c1] = __float2bfloat16(h1 - __bfloat162float(b1v));
    }
    __syncwarp();

    // ---- layer 2 GEMM via mma.sync, 3-term bf16 split ----
    // A frag lane addressing (m16n8k16, ldmatrix.x4 block order a0..a3):
    const uint32_t aoff = ((((lane >> 3) & 1) * 8 + (lane & 7)) * ROWB)
                        + ((lane >> 4) & 1) * 16;
    // B frag lane addressing (blocks: (n0-7,k0-15),(n0-7,k16-31),(n8-15,..),(..)):
    const uint32_t boff = ((((lane >> 4) & 1) * 8 + (lane & 7)) * ROWB)
                        + ((lane >> 3) & 1) * 16;

    const uint32_t baseAh = smem_u32(smem + OF_AH + wid * 32 * ROWB) + aoff;
    const uint32_t baseAl = smem_u32(smem + OF_AL + wid * 32 * ROWB) + aoff;
    const uint32_t baseBh = smem_u32(smem + OF_BH) + boff;
    const uint32_t baseBl = smem_u32(smem + OF_BL) + boff;

    float run[16];
    #pragma unroll
    for (int i = 0; i < 16; i++) run[i] = NEG_;

    const int nmt = (npts > 16) ? 2 : 1;

    #pragma unroll 2
    for (int mt = 0; mt < nmt; mt++) {
        float D[8][4];
        #pragma unroll
        for (int i = 0; i < 8; i++)
            #pragma unroll
            for (int q = 0; q < 4; q++) D[i][q] = 0.0f;

        #pragma unroll
        for (int kt = 0; kt < 4; kt++) {
            uint32_t ah0, ah1, ah2, ah3, al0, al1, al2, al3;
            ldsm4(baseAh + mt * 16 * ROWB + kt * 32, ah0, ah1, ah2, ah3);
            ldsm4(baseAl + mt * 16 * ROWB + kt * 32, al0, al1, al2, al3);
            #pragma unroll
            for (int np = 0; np < 4; np++) {
                uint32_t bh0, bh1, bh2, bh3, bl0, bl1, bl2, bl3;
                ldsm4(baseBh + np * 16 * ROWB + kt * 32, bh0, bh1, bh2, bh3);
                ldsm4(baseBl + np * 16 * ROWB + kt * 32, bl0, bl1, bl2, bl3);
                mma16816(D[2*np+0], ah0, ah1, ah2, ah3, bh0, bh1);
                mma16816(D[2*np+1], ah0, ah1, ah2, ah3, bh2, bh3);
                mma16816(D[2*np+0], ah0, ah1, ah2, ah3, bl0, bl1);
                mma16816(D[2*np+1], ah0, ah1, ah2, ah3, bl2, bl3);
                mma16816(D[2*np+0], al0, al1, al2, al3, bh0, bh1);
                mma16816(D[2*np+1], al0, al1, al2, al3, bh2, bh3);
            }
        }

        // mask invalid rows, fold into running per-column maxes
        const int rlo = mt * 16 + (lane >> 2);
        const bool v0 = (rlo < npts);
        const bool v2 = (rlo + 8 < npts);
        #pragma unroll
        for (int nt = 0; nt < 8; nt++) {
            const float e0 = v0 ? D[nt][0] : NEG_;
            const float e1 = v0 ? D[nt][1] : NEG_;
            const float e2 = v2 ? D[nt][2] : NEG_;
            const float e3 = v2 ? D[nt][3] : NEG_;
            run[2*nt+0] = fmaxf(run[2*nt+0], fmaxf(e0, e2));
            run[2*nt+1] = fmaxf(run[2*nt+1], fmaxf(e1, e3));
        }
    }

    // cross-lane max over the 8 row-groups (lanes with equal lane%4)
    #pragma unroll
    for (int i = 0; i < 16; i++) {
        run[i] = fmaxf(run[i], __shfl_xor_sync(0xFFFFFFFFu, run[i], 4));
        run[i] = fmaxf(run[i], __shfl_xor_sync(0xFFFFFFFFu, run[i], 8));
        run[i] = fmaxf(run[i], __shfl_xor_sync(0xFFFFFFFFu, run[i], 16));
    }

    if (lane < 4) {
        #pragma unroll
        for (int nt = 0; nt < 8; nt++) {
            const int col = nt * 8 + lane * 2;
            float2 o;
            o.x = fmaxf(run[2*nt+0] + d_t2f[col + 0], 0.0f);
            o.y = fmaxf(run[2*nt+1] + d_t2f[col + 1], 0.0f);
            *(float2*)(out + p * 64 + col) = o;
        }
    }
}

extern "C" void kernel_launch(void* const* d_in, const int* in_sizes, int n_in,
                              void* d_out, int out_size) {
    const float* pillars = (const float*)d_in[0];   // (P,32,4) f32
    const void*  coords  = d_in[1];                 // (P,2) int32 or int64
    const void*  npts    = d_in[2];                 // (P,)  int32 or int64
    const float* W1    = (const float*)d_in[3];
    const float* b1    = (const float*)d_in[4];
    const float* g1    = (const float*)d_in[5];
    const float* beta1 = (const float*)d_in[6];
    const float* m1    = (const float*)d_in[7];
    const float* v1    = (const float*)d_in[8];
    const float* W2    = (const float*)d_in[9];
    const float* b2    = (const float*)d_in[10];
    const float* g2    = (const float*)d_in[11];
    const float* beta2 = (const float*)d_in[12];
    const float* m2    = (const float*)d_in[13];
    const float* v2    = (const float*)d_in[14];

    const int P = in_sizes[2];

    static int smem_set = 0;
    if (!smem_set) {
        cudaFuncSetAttribute(pfn_mma, cudaFuncAttributeMaxDynamicSharedMemorySize,
                             SMEM_TOT);
        smem_set = 1;
    }

    const int nwords = (P >= 64) ? 129 : (2 * P);
    pfn_detect<<<1, 1>>>((const int*)npts, nwords);
    pfn_prep<<<1, 64>>>(W1, b1, g1, beta1, m1, v1, W2, b2, g2, beta2, m2, v2);

    const int blocks = (P + 3) / 4;
    pfn_mma<<<blocks, 128, SMEM_TOT>>>(
        (const float4*)pillars, coords, npts, (float*)d_out, P);
}

// round 11
// speedup vs baseline: 5.0837x; 1.7391x over previous
#include <cuda_runtime.h>
#include <cuda_fp16.h>
#include <cstdint>

#define RES_   0.16f
#define XMIN_ (-51.2f)
#define YMIN_ (-51.2f)
#define EPS_   1e-5f
#define NEG_  (-1000000000.0f)

// Folded params (device globals: allocation-free).
__device__ float d_A[8 * 64];
__device__ float d_t2f[64];
__device__ __align__(16) __half d_Bh[64 * 64];  // [n][k] = fp16(W2f[k][n])
__device__ int d_i64flag;

__device__ __forceinline__ uint32_t smem_u32(const void* p) {
    uint32_t a;
    asm("{ .reg .u64 t; cvta.to.shared.u64 t, %1; cvt.u32.u64 %0, t; }" : "=r"(a) : "l"(p));
    return a;
}
__device__ __forceinline__ void ldsm4(uint32_t a, uint32_t& r0, uint32_t& r1,
                                      uint32_t& r2, uint32_t& r3) {
    asm volatile("ldmatrix.sync.aligned.m8n8.x4.shared.b16 {%0,%1,%2,%3}, [%4];"
                 : "=r"(r0), "=r"(r1), "=r"(r2), "=r"(r3) : "r"(a));
}
__device__ __forceinline__ void mma16816(float* d, uint32_t a0, uint32_t a1,
                                         uint32_t a2, uint32_t a3,
                                         uint32_t b0, uint32_t b1) {
    asm volatile(
        "mma.sync.aligned.m16n8k16.row.col.f32.f16.f16.f32 "
        "{%0,%1,%2,%3}, {%4,%5,%6,%7}, {%8,%9}, {%0,%1,%2,%3};"
        : "+f"(d[0]), "+f"(d[1]), "+f"(d[2]), "+f"(d[3])
        : "r"(a0), "r"(a1), "r"(a2), "r"(a3), "r"(b0), "r"(b1));
}

// prep (warps 0-1) + int-width detect (warp 2), one launch
__global__ void pfn_prep(const float* __restrict__ W1, const float* __restrict__ b1,
                         const float* __restrict__ g1, const float* __restrict__ beta1,
                         const float* __restrict__ m1, const float* __restrict__ v1,
                         const float* __restrict__ W2, const float* __restrict__ b2,
                         const float* __restrict__ g2, const float* __restrict__ beta2,
                         const float* __restrict__ m2, const float* __restrict__ v2,
                         const int* __restrict__ npts_i32, int nwords) {
    const int t = threadIdx.x;
    if (t < 64) {
        const int c = t;
        float s1 = g1[c] * rsqrtf(v1[c] + EPS_);
        float w0 = W1[0*64+c], w1 = W1[1*64+c], w2 = W1[2*64+c];
        float w3 = W1[3*64+c], w4 = W1[4*64+c], w5 = W1[5*64+c];
        float w6 = W1[6*64+c], w7 = W1[7*64+c], w8 = W1[8*64+c];
        d_A[0*64+c] = (w0 + w4 + w7) * s1;
        d_A[1*64+c] = (w1 + w5 + w8) * s1;
        d_A[2*64+c] = (w2 + w6) * s1;
        d_A[3*64+c] = w3 * s1;
        d_A[4*64+c] = (w4 + w7) * s1;
        d_A[5*64+c] = (w5 + w8) * s1;
        d_A[6*64+c] = w6 * s1;
        d_A[7*64+c] = (b1[c] - m1[c]) * s1 + beta1[c];

        float s2 = g2[c] * rsqrtf(v2[c] + EPS_);
        for (int k = 0; k < 64; k++)
            d_Bh[c*64 + k] = __float2half(W2[k*64 + c] * s2);   // [n=c][k]
        d_t2f[c] = (b2[c] - m2[c]) * s2 + beta2[c];
    } else if (t == 64) {
        int f = 1;
        #pragma unroll 1
        for (int i = 1; i < nwords; i += 2) {
            if (npts_i32[i] != 0) { f = 0; break; }
        }
        d_i64flag = f;
    }
}

// ---------------- main kernel: 1 warp = 1 pillar, 4 pillars/CTA ----------------
// SMEM (144B row stride = 128B data + 16B pad):
//   A : 4 warps x 32 rows x 144B = 18432
//   B : 64 rows x 144B           =  9216
#define ROWB     144
#define OF_A     0
#define OF_B     18432
#define SMEM_TOT 27648

// NMT m-tiles of GEMM: D[NMT*8][4] accumulators, B frags loaded once per kt.
template <int NMT>
__device__ __forceinline__ void gemm_tiles(uint32_t baseA, uint32_t baseB,
                                           float (*D)[4]) {
    #pragma unroll
    for (int kt = 0; kt < 4; kt++) {
        uint32_t a[NMT][4];
        #pragma unroll
        for (int mt = 0; mt < NMT; mt++)
            ldsm4(baseA + mt * 16 * ROWB + kt * 32,
                  a[mt][0], a[mt][1], a[mt][2], a[mt][3]);
        #pragma unroll
        for (int np = 0; np < 4; np++) {
            uint32_t b0, b1, b2, b3;
            ldsm4(baseB + np * 16 * ROWB + kt * 32, b0, b1, b2, b3);
            #pragma unroll
            for (int mt = 0; mt < NMT; mt++) {
                mma16816(D[mt*8 + 2*np + 0], a[mt][0], a[mt][1], a[mt][2], a[mt][3], b0, b1);
                mma16816(D[mt*8 + 2*np + 1], a[mt][0], a[mt][1], a[mt][2], a[mt][3], b2, b3);
            }
        }
    }
}

__device__ __forceinline__ void fold_tile(const float (*D)[4], int mt, int npts,
                                          int lane, float* run) {
    const int rlo = mt * 16 + (lane >> 2);
    const bool v0 = (rlo < npts);
    const bool v2 = (rlo + 8 < npts);
    #pragma unroll
    for (int nt = 0; nt < 8; nt++) {
        const float e0 = v0 ? D[mt*8 + nt][0] : NEG_;
        const float e1 = v0 ? D[mt*8 + nt][1] : NEG_;
        const float e2 = v2 ? D[mt*8 + nt][2] : NEG_;
        const float e3 = v2 ? D[mt*8 + nt][3] : NEG_;
        run[2*nt+0] = fmaxf(run[2*nt+0], fmaxf(e0, e2));
        run[2*nt+1] = fmaxf(run[2*nt+1], fmaxf(e1, e3));
    }
}

__global__ void __launch_bounds__(128) pfn_mma(
    const float4* __restrict__ pillars,
    const void*  __restrict__ coords_raw,
    const void*  __restrict__ npts_raw,
    float* __restrict__ out, int P)
{
    extern __shared__ __align__(128) unsigned char smem[];
    const int tid  = threadIdx.x;
    const int wid  = tid >> 5;
    const int lane = tid & 31;

    // ---- B tile -> smem (shared by all 4 warps) ----
    {
        const uint4* gh = (const uint4*)d_Bh;   // 64 rows x 8 uint4
        #pragma unroll
        for (int g = tid; g < 512; g += 128) {
            const int row = g >> 3, c = g & 7;
            *(uint4*)(smem + OF_B + row*ROWB + c*16) = gh[g];
        }
    }
    __syncthreads();

    const int  p  = blockIdx.x * 4 + wid;
    const bool pv = (p < P);
    const int  pe = pv ? p : 0;

    int npts; float crow, ccol;
    if (d_i64flag) {
        npts = (int)((const long long*)npts_raw)[pe];
        crow = (float)((const long long*)coords_raw)[pe*2 + 0];
        ccol = (float)((const long long*)coords_raw)[pe*2 + 1];
    } else {
        npts = ((const int*)npts_raw)[pe];
        crow = (float)((const int*)coords_raw)[pe*2 + 0];
        ccol = (float)((const int*)coords_raw)[pe*2 + 1];
    }
    npts = min(max(npts, 0), 32);
    if (!pv) return;

    if (npts == 0) {
        out[p*64 + lane]      = NEG_;
        out[p*64 + lane + 32] = NEG_;
        return;
    }

    // ---- layer 1: folded BN + rank-4 collapse; fp16 into A tile ----
    const float4 pt = pillars[pe * 32 + lane];
    float zs = (lane < npts) ? pt.z : 0.0f;
    #pragma unroll
    for (int o = 16; o; o >>= 1) zs += __shfl_xor_sync(0xFFFFFFFFu, zs, o);
    const float zm = zs / fmaxf((float)npts, 1.0f);

    const float xc = (ccol + 0.5f) * RES_ + XMIN_;
    const float yc = (crow + 0.5f) * RES_ + YMIN_;

    const int c0 = lane, c1 = lane + 32;
    const float ax0 = d_A[0*64+c0], ay0 = d_A[1*64+c0], az0 = d_A[2*64+c0], ar0 = d_A[3*64+c0];
    const float ax1 = d_A[0*64+c1], ay1 = d_A[1*64+c1], az1 = d_A[2*64+c1], ar1 = d_A[3*64+c1];
    const float bias0 = d_A[7*64+c0] - xc*d_A[4*64+c0] - yc*d_A[5*64+c0] - zm*d_A[6*64+c0];
    const float bias1 = d_A[7*64+c1] - xc*d_A[4*64+c1] - yc*d_A[5*64+c1] - zm*d_A[6*64+c1];

    __half* ah = (__half*)(smem + OF_A + wid * 32 * ROWB);
    const int rw = ROWB / 2;   // fp16 per row (72)

    for (int j = 0; j < npts; j++) {
        const float x  = __shfl_sync(0xFFFFFFFFu, pt.x, j);
        const float y  = __shfl_sync(0xFFFFFFFFu, pt.y, j);
        const float zz = __shfl_sync(0xFFFFFFFFu, pt.z, j);
        const float r  = __shfl_sync(0xFFFFFFFFu, pt.w, j);

        float h0 = fmaf(ax0, x, fmaf(ay0, y, fmaf(az0, zz, fmaf(ar0, r, bias0))));
        float h1 = fmaf(ax1, x, fmaf(ay1, y, fmaf(az1, zz, fmaf(ar1, r, bias1))));
        h0 = fmaxf(h0, 0.0f);
        h1 = fmaxf(h1, 0.0f);

        ah[j*rw + c0] = __float2half(h0);
        ah[j*rw + c1] = __float2half(h1);
    }
    __syncwarp();

    // ---- layer 2 GEMM via fp16 mma.sync (single term) ----
    const uint32_t aoff = ((((lane >> 3) & 1) * 8 + (lane & 7)) * ROWB)
                        + ((lane >> 4) & 1) * 16;
    const uint32_t boff = ((((lane >> 4) & 1) * 8 + (lane & 7)) * ROWB)
                        + ((lane >> 3) & 1) * 16;

    const uint32_t baseA = smem_u32(smem + OF_A + wid * 32 * ROWB) + aoff;
    const uint32_t baseB = smem_u32(smem + OF_B) + boff;

    float run[16];
    #pragma unroll
    for (int i = 0; i < 16; i++) run[i] = NEG_;

    if (npts > 16) {
        float D[16][4];
        #pragma unroll
        for (int i = 0; i < 16; i++)
            #pragma unroll
            for (int q = 0; q < 4; q++) D[i][q] = 0.0f;
        gemm_tiles<2>(baseA, baseB, D);
        fold_tile(D, 0, npts, lane, run);
        fold_tile(D, 1, npts, lane, run);
    } else {
        float D[8][4];
        #pragma unroll
        for (int i = 0; i < 8; i++)
            #pragma unroll
            for (int q = 0; q < 4; q++) D[i][q] = 0.0f;
        gemm_tiles<1>(baseA, baseB, D);
        fold_tile(D, 0, npts, lane, run);
    }

    // cross-lane max over the 8 row-groups (lanes with equal lane%4)
    #pragma unroll
    for (int i = 0; i < 16; i++) {
        run[i] = fmaxf(run[i], __shfl_xor_sync(0xFFFFFFFFu, run[i], 4));
        run[i] = fmaxf(run[i], __shfl_xor_sync(0xFFFFFFFFu, run[i], 8));
        run[i] = fmaxf(run[i], __shfl_xor_sync(0xFFFFFFFFu, run[i], 16));
    }

    if (lane < 4) {
        #pragma unroll
        for (int nt = 0; nt < 8; nt++) {
            const int col = nt * 8 + lane * 2;
            float2 o;
            o.x = fmaxf(run[2*nt+0] + d_t2f[col + 0], 0.0f);
            o.y = fmaxf(run[2*nt+1] + d_t2f[col + 1], 0.0f);
            *(float2*)(out + p * 64 + col) = o;
        }
    }
}

extern "C" void kernel_launch(void* const* d_in, const int* in_sizes, int n_in,
                              void* d_out, int out_size) {
    const float* pillars = (const float*)d_in[0];   // (P,32,4) f32
    const void*  coords  = d_in[1];                 // (P,2) int32 or int64
    const void*  npts    = d_in[2];                 // (P,)  int32 or int64
    const float* W1    = (const float*)d_in[3];
    const float* b1    = (const float*)d_in[4];
    const float* g1    = (const float*)d_in[5];
    const float* beta1 = (const float*)d_in[6];
    const float* m1    = (const float*)d_in[7];
    const float* v1    = (const float*)d_in[8];
    const float* W2    = (const float*)d_in[9];
    const float* b2    = (const float*)d_in[10];
    const float* g2    = (const float*)d_in[11];
    const float* beta2 = (const float*)d_in[12];
    const float* m2    = (const float*)d_in[13];
    const float* v2    = (const float*)d_in[14];

    const int P = in_sizes[2];

    static int smem_set = 0;
    if (!smem_set) {
        cudaFuncSetAttribute(pfn_mma, cudaFuncAttributeMaxDynamicSharedMemorySize,
                             SMEM_TOT);
        smem_set = 1;
    }

    const int nwords = (P >= 64) ? 129 : (2 * P);
    pfn_prep<<<1, 128>>>(W1, b1, g1, beta1, m1, v1, W2, b2, g2, beta2, m2, v2,
                         (const int*)npts, nwords);

    const int blocks = (P + 3) / 4;
    pfn_mma<<<blocks, 128, SMEM_TOT>>>(
        (const float4*)pillars, coords, npts, (float*)d_out, P);
}

// round 14
// speedup vs baseline: 5.7105x; 1.1233x over previous
#include <cuda_runtime.h>
#include <cuda_fp16.h>
#include <cstdint>

#define RES_   0.16f
#define XMIN_ (-51.2f)
#define YMIN_ (-51.2f)
#define EPS_   1e-5f
#define NEG_  (-1000000000.0f)
#define G_PIL  8

// Folded params (device globals: allocation-free).
__device__ float d_A[8 * 64];
__device__ float d_t2f[64];
__device__ __align__(16) __half d_Bh[64 * 64];  // [n][k] = fp16(W2f[k][n])
__device__ int d_i64flag;

__device__ __forceinline__ uint32_t smem_u32(const void* p) {
    uint32_t a;
    asm("{ .reg .u64 t; cvta.to.shared.u64 t, %1; cvt.u32.u64 %0, t; }" : "=r"(a) : "l"(p));
    return a;
}
__device__ __forceinline__ void ldsm4(uint32_t a, uint32_t& r0, uint32_t& r1,
                                      uint32_t& r2, uint32_t& r3) {
    asm volatile("ldmatrix.sync.aligned.m8n8.x4.shared.b16 {%0,%1,%2,%3}, [%4];"
                 : "=r"(r0), "=r"(r1), "=r"(r2), "=r"(r3) : "r"(a));
}
__device__ __forceinline__ void mma16816(float* d, uint32_t a0, uint32_t a1,
                                         uint32_t a2, uint32_t a3,
                                         uint32_t b0, uint32_t b1) {
    asm volatile(
        "mma.sync.aligned.m16n8k16.row.col.f32.f16.f16.f32 "
        "{%0,%1,%2,%3}, {%4,%5,%6,%7}, {%8,%9}, {%0,%1,%2,%3};"
        : "+f"(d[0]), "+f"(d[1]), "+f"(d[2]), "+f"(d[3])
        : "r"(a0), "r"(a1), "r"(a2), "r"(a3), "r"(b0), "r"(b1));
}

// prep (lanes 0-63) + int-width detect (lane 64), one launch
__global__ void pfn_prep(const float* __restrict__ W1, const float* __restrict__ b1,
                         const float* __restrict__ g1, const float* __restrict__ beta1,
                         const float* __restrict__ m1, const float* __restrict__ v1,
                         const float* __restrict__ W2, const float* __restrict__ b2,
                         const float* __restrict__ g2, const float* __restrict__ beta2,
                         const float* __restrict__ m2, const float* __restrict__ v2,
                         const int* __restrict__ npts_i32, int nwords) {
    const int t = threadIdx.x;
    if (t < 64) {
        const int c = t;
        float s1 = g1[c] * rsqrtf(v1[c] + EPS_);
        float w0 = W1[0*64+c], w1 = W1[1*64+c], w2 = W1[2*64+c];
        float w3 = W1[3*64+c], w4 = W1[4*64+c], w5 = W1[5*64+c];
        float w6 = W1[6*64+c], w7 = W1[7*64+c], w8 = W1[8*64+c];
        d_A[0*64+c] = (w0 + w4 + w7) * s1;
        d_A[1*64+c] = (w1 + w5 + w8) * s1;
        d_A[2*64+c] = (w2 + w6) * s1;
        d_A[3*64+c] = w3 * s1;
        d_A[4*64+c] = (w4 + w7) * s1;
        d_A[5*64+c] = (w5 + w8) * s1;
        d_A[6*64+c] = w6 * s1;
        d_A[7*64+c] = (b1[c] - m1[c]) * s1 + beta1[c];

        float s2 = g2[c] * rsqrtf(v2[c] + EPS_);
        for (int k = 0; k < 64; k++)
            d_Bh[c*64 + k] = __float2half(W2[k*64 + c] * s2);   // [n=c][k]
        d_t2f[c] = (b2[c] - m2[c]) * s2 + beta2[c];
    } else if (t == 64) {
        int f = 1;
        #pragma unroll 1
        for (int i = 1; i < nwords; i += 2) {
            if (npts_i32[i] != 0) { f = 0; break; }
        }
        d_i64flag = f;
    }
}

// ---------------- main kernel: 1 warp = 8 pillars, 4 warps/CTA ----------------
// SMEM (144B row stride = 128B data + 16B pad):
//   A : 4 warps x 32 rows x 144B = 18432
//   B : 64 rows x 144B           =  9216
#define ROWB     144
#define OF_A     0
#define OF_B     18432
#define SMEM_TOT 27648

__global__ void __launch_bounds__(128) pfn_mma(
    const float4* __restrict__ pillars,
    const void*  __restrict__ coords_raw,
    const void*  __restrict__ npts_raw,
    float* __restrict__ out, int P)
{
    extern __shared__ __align__(128) unsigned char smem[];
    const int tid  = threadIdx.x;
    const int wid  = tid >> 5;
    const int lane = tid & 31;

    // ---- B tile -> smem (once per CTA) ----
    {
        const uint4* gh = (const uint4*)d_Bh;   // 64 rows x 8 uint4
        #pragma unroll
        for (int g = tid; g < 512; g += 128) {
            const int row = g >> 3, c = g & 7;
            *(uint4*)(smem + OF_B + row*ROWB + c*16) = gh[g];
        }
    }
    __syncthreads();

    // ---- B fragments -> registers (once per warp; reused for all pillars) ----
    const uint32_t boff = ((((lane >> 4) & 1) * 8 + (lane & 7)) * ROWB)
                        + ((lane >> 3) & 1) * 16;
    const uint32_t baseB = smem_u32(smem + OF_B) + boff;
    uint32_t Bf[4][4][4];   // [np][kt][r]
    #pragma unroll
    for (int np = 0; np < 4; np++)
        #pragma unroll
        for (int kt = 0; kt < 4; kt++)
            ldsm4(baseB + np * 16 * ROWB + kt * 32,
                  Bf[np][kt][0], Bf[np][kt][1], Bf[np][kt][2], Bf[np][kt][3]);

    // ---- hoisted per-channel constants (lane owns channels 2l, 2l+1) ----
    const int c0 = lane * 2, c1 = lane * 2 + 1;
    const float ax0 = d_A[0*64+c0], ay0 = d_A[1*64+c0], az0 = d_A[2*64+c0], ar0 = d_A[3*64+c0];
    const float ax1 = d_A[0*64+c1], ay1 = d_A[1*64+c1], az1 = d_A[2*64+c1], ar1 = d_A[3*64+c1];
    const float k40 = d_A[4*64+c0], k50 = d_A[5*64+c0], k60 = d_A[6*64+c0], k70 = d_A[7*64+c0];
    const float k41 = d_A[4*64+c1], k51 = d_A[5*64+c1], k61 = d_A[6*64+c1], k71 = d_A[7*64+c1];

    // hoisted output biases (used by lanes 0-3 in epilogue)
    const int colb = (lane & 3) * 2;
    float t2a[8], t2b[8];
    #pragma unroll
    for (int nt = 0; nt < 8; nt++) {
        t2a[nt] = d_t2f[nt*8 + colb + 0];
        t2b[nt] = d_t2f[nt*8 + colb + 1];
    }

    const int i64 = d_i64flag;

    // ldmatrix A lane addressing
    const uint32_t aoff = ((((lane >> 3) & 1) * 8 + (lane & 7)) * ROWB)
                        + ((lane >> 4) & 1) * 16;
    const uint32_t baseA = smem_u32(smem + OF_A + wid * 32 * ROWB) + aoff;
    uint32_t* arow = (uint32_t*)(smem + OF_A + wid * 32 * ROWB);
    const int rw4 = ROWB / 4;   // u32 per row

    const int pfirst = (blockIdx.x * 4 + wid) * G_PIL;

    // ---- prefetch pillar 0 ----
    int npts_n = 0; float crow_n = 0.f, ccol_n = 0.f;
    float4 pt_n = make_float4(0.f, 0.f, 0.f, 0.f);
    if (pfirst < P) {
        if (i64) {
            npts_n = (int)((const long long*)npts_raw)[pfirst];
            crow_n = (float)((const long long*)coords_raw)[pfirst*2 + 0];
            ccol_n = (float)((const long long*)coords_raw)[pfirst*2 + 1];
        } else {
            npts_n = ((const int*)npts_raw)[pfirst];
            crow_n = (float)((const int*)coords_raw)[pfirst*2 + 0];
            ccol_n = (float)((const int*)coords_raw)[pfirst*2 + 1];
        }
        npts_n = min(max(npts_n, 0), 32);
        pt_n = pillars[pfirst * 32 + lane];
    }

    #pragma unroll 1
    for (int g = 0; g < G_PIL; g++) {
        const int p = pfirst + g;
        if (p >= P) break;

        const int npts = npts_n;
        const float crow = crow_n, ccol = ccol_n;
        const float4 pt = pt_n;

        // prefetch next pillar (overlaps layer-1 + GEMM)
        const int pn = p + 1;
        if (g + 1 < G_PIL && pn < P) {
            if (i64) {
                npts_n = (int)((const long long*)npts_raw)[pn];
                crow_n = (float)((const long long*)coords_raw)[pn*2 + 0];
                ccol_n = (float)((const long long*)coords_raw)[pn*2 + 1];
            } else {
                npts_n = ((const int*)npts_raw)[pn];
                crow_n = (float)((const int*)coords_raw)[pn*2 + 0];
                ccol_n = (float)((const int*)coords_raw)[pn*2 + 1];
            }
            npts_n = min(max(npts_n, 0), 32);
            pt_n = pillars[pn * 32 + lane];
        }

        if (npts == 0) {
            out[p*64 + lane]      = NEG_;
            out[p*64 + lane + 32] = NEG_;
            continue;
        }

        // ---- layer 1: folded BN + rank-4 collapse -> packed half2 A tile ----
        float zs = (lane < npts) ? pt.z : 0.0f;
        #pragma unroll
        for (int o = 16; o; o >>= 1) zs += __shfl_xor_sync(0xFFFFFFFFu, zs, o);
        const float zm = zs / fmaxf((float)npts, 1.0f);

        const float xc = (ccol + 0.5f) * RES_ + XMIN_;
        const float yc = (crow + 0.5f) * RES_ + YMIN_;
        const float bias0 = k70 - xc*k40 - yc*k50 - zm*k60;
        const float bias1 = k71 - xc*k41 - yc*k51 - zm*k61;

        for (int j = 0; j < npts; j++) {
            const float x  = __shfl_sync(0xFFFFFFFFu, pt.x, j);
            const float y  = __shfl_sync(0xFFFFFFFFu, pt.y, j);
            const float zz = __shfl_sync(0xFFFFFFFFu, pt.z, j);
            const float r  = __shfl_sync(0xFFFFFFFFu, pt.w, j);

            float h0 = fmaf(ax0, x, fmaf(ay0, y, fmaf(az0, zz, fmaf(ar0, r, bias0))));
            float h1 = fmaf(ax1, x, fmaf(ay1, y, fmaf(az1, zz, fmaf(ar1, r, bias1))));
            h0 = fmaxf(h0, 0.0f);
            h1 = fmaxf(h1, 0.0f);

            const __half2 hv = __floats2half2_rn(h0, h1);
            arow[j * rw4 + lane] = *(const uint32_t*)&hv;   // STS.32, conflict-free
        }
        __syncwarp();

        // ---- layer 2 GEMM: A from smem, B from registers ----
        float run[16];
        #pragma unroll
        for (int i = 0; i < 16; i++) run[i] = NEG_;

        const int nmt = (npts > 16) ? 2 : 1;
        #pragma unroll 1
        for (int mt = 0; mt < nmt; mt++) {
            float D[8][4];
            #pragma unroll
            for (int i = 0; i < 8; i++)
                #pragma unroll
                for (int q = 0; q < 4; q++) D[i][q] = 0.0f;

            #pragma unroll
            for (int kt = 0; kt < 4; kt++) {
                uint32_t a0, a1, a2, a3;
                ldsm4(baseA + mt * 16 * ROWB + kt * 32, a0, a1, a2, a3);
                #pragma unroll
                for (int np = 0; np < 4; np++) {
                    mma16816(D[2*np+0], a0, a1, a2, a3, Bf[np][kt][0], Bf[np][kt][1]);
                    mma16816(D[2*np+1], a0, a1, a2, a3, Bf[np][kt][2], Bf[np][kt][3]);
                }
            }

            const int rlo = mt * 16 + (lane >> 2);
            const bool v0 = (rlo < npts);
            const bool v2 = (rlo + 8 < npts);
            #pragma unroll
            for (int nt = 0; nt < 8; nt++) {
                const float e0 = v0 ? D[nt][0] : NEG_;
                const float e1 = v0 ? D[nt][1] : NEG_;
                const float e2 = v2 ? D[nt][2] : NEG_;
                const float e3 = v2 ? D[nt][3] : NEG_;
                run[2*nt+0] = fmaxf(run[2*nt+0], fmaxf(e0, e2));
                run[2*nt+1] = fmaxf(run[2*nt+1], fmaxf(e1, e3));
            }
        }
        __syncwarp();   // A tile reads done before next pillar overwrites

        // cross-lane max over the 8 row-groups
        #pragma unroll
        for (int i = 0; i < 16; i++) {
            run[i] = fmaxf(run[i], __shfl_xor_sync(0xFFFFFFFFu, run[i], 4));
            run[i] = fmaxf(run[i], __shfl_xor_sync(0xFFFFFFFFu, run[i], 8));
            run[i] = fmaxf(run[i], __shfl_xor_sync(0xFFFFFFFFu, run[i], 16));
        }

        if (lane < 4) {
            #pragma unroll
            for (int nt = 0; nt < 8; nt++) {
                const int col = nt * 8 + lane * 2;
                float2 o;
                o.x = fmaxf(run[2*nt+0] + t2a[nt], 0.0f);
                o.y = fmaxf(run[2*nt+1] + t2b[nt], 0.0f);
                *(float2*)(out + p * 64 + col) = o;
            }
        }
    }
}

extern "C" void kernel_launch(void* const* d_in, const int* in_sizes, int n_in,
                              void* d_out, int out_size) {
    const float* pillars = (const float*)d_in[0];   // (P,32,4) f32
    const void*  coords  = d_in[1];                 // (P,2) int32 or int64
    const void*  npts    = d_in[2];                 // (P,)  int32 or int64
    const float* W1    = (const float*)d_in[3];
    const float* b1    = (const float*)d_in[4];
    const float* g1    = (const float*)d_in[5];
    const float* beta1 = (const float*)d_in[6];
    const float* m1    = (const float*)d_in[7];
    const float* v1    = (const float*)d_in[8];
    const float* W2    = (const float*)d_in[9];
    const float* b2    = (const float*)d_in[10];
    const float* g2    = (const float*)d_in[11];
    const float* beta2 = (const float*)d_in[12];
    const float* m2    = (const float*)d_in[13];
    const float* v2    = (const float*)d_in[14];

    const int P = in_sizes[2];

    const int nwords = (P >= 64) ? 129 : (2 * P);
    pfn_prep<<<1, 128>>>(W1, b1, g1, beta1, m1, v1, W2, b2, g2, beta2, m2, v2,
                         (const int*)npts, nwords);

    const int blocks = (P + 4 * G_PIL - 1) / (4 * G_PIL);
    pfn_mma<<<blocks, 128, SMEM_TOT>>>(
        (const float4*)pillars, coords, npts, (float*)d_out, P);
}

// round 15
// speedup vs baseline: 6.8588x; 1.2011x over previous
#include <cuda_runtime.h>
#include <cuda_fp16.h>
#include <cstdint>

#define RES_   0.16f
#define XMIN_ (-51.2f)
#define YMIN_ (-51.2f)
#define EPS_   1e-5f
#define NEG_  (-1000000000.0f)
#define G_PIL  8

// Folded params (device globals: allocation-free).
__device__ __align__(8) float d_t2f[64];
__device__ __align__(16) __half d_Bh[64 * 64];    // [n][k] = fp16(W2f[k][n])
__device__ __align__(16) uint32_t d_B1u[64 * 4];  // [n][q] = half2 B1 frag pairs
__device__ int d_i64flag;

__device__ __forceinline__ uint32_t smem_u32(const void* p) {
    uint32_t a;
    asm("{ .reg .u64 t; cvta.to.shared.u64 t, %1; cvt.u32.u64 %0, t; }" : "=r"(a) : "l"(p));
    return a;
}
__device__ __forceinline__ void ldsm4(uint32_t a, uint32_t& r0, uint32_t& r1,
                                      uint32_t& r2, uint32_t& r3) {
    asm volatile("ldmatrix.sync.aligned.m8n8.x4.shared.b16 {%0,%1,%2,%3}, [%4];"
                 : "=r"(r0), "=r"(r1), "=r"(r2), "=r"(r3) : "r"(a));
}
__device__ __forceinline__ void mma16816(float* d, uint32_t a0, uint32_t a1,
                                         uint32_t a2, uint32_t a3,
                                         uint32_t b0, uint32_t b1) {
    asm volatile(
        "mma.sync.aligned.m16n8k16.row.col.f32.f16.f16.f32 "
        "{%0,%1,%2,%3}, {%4,%5,%6,%7}, {%8,%9}, {%0,%1,%2,%3};"
        : "+f"(d[0]), "+f"(d[1]), "+f"(d[2]), "+f"(d[3])
        : "r"(a0), "r"(a1), "r"(a2), "r"(a3), "r"(b0), "r"(b1));
}
__device__ __forceinline__ void mma1688(float* d, uint32_t a0, uint32_t a1,
                                        uint32_t b0) {
    asm volatile(
        "mma.sync.aligned.m16n8k8.row.col.f32.f16.f16.f32 "
        "{%0,%1,%2,%3}, {%4,%5}, {%6}, {%0,%1,%2,%3};"
        : "+f"(d[0]), "+f"(d[1]), "+f"(d[2]), "+f"(d[3])
        : "r"(a0), "r"(a1), "r"(b0));
}
__device__ __forceinline__ uint32_t pkh2(float lo, float hi) {
    const __half2 h = __floats2half2_rn(lo, hi);
    return *(const uint32_t*)&h;
}

// prep (lanes 0-63) + int-width detect (lane 64), one launch
__global__ void pfn_prep(const float* __restrict__ W1, const float* __restrict__ b1,
                         const float* __restrict__ g1, const float* __restrict__ beta1,
                         const float* __restrict__ m1, const float* __restrict__ v1,
                         const float* __restrict__ W2, const float* __restrict__ b2,
                         const float* __restrict__ g2, const float* __restrict__ beta2,
                         const float* __restrict__ m2, const float* __restrict__ v2,
                         const int* __restrict__ npts_i32, int nwords) {
    const int t = threadIdx.x;
    if (t < 64) {
        const int c = t;
        float s1 = g1[c] * rsqrtf(v1[c] + EPS_);
        float w0 = W1[0*64+c], w1 = W1[1*64+c], w2 = W1[2*64+c];
        float w3 = W1[3*64+c], w4 = W1[4*64+c], w5 = W1[5*64+c];
        float w6 = W1[6*64+c], w7 = W1[7*64+c], w8 = W1[8*64+c];
        const float ax = (w0 + w4 + w7) * s1;       // x
        const float ay = (w1 + w5 + w8) * s1;       // y
        const float az = (w2 + w6) * s1;            // z
        const float ar = w3 * s1;                   // r
        const float k4 = (w4 + w7) * s1;            // xc coeff
        const float k5 = (w5 + w8) * s1;            // yc coeff
        const float k6 = w6 * s1;                   // zm coeff
        const float k7 = (b1[c] - m1[c]) * s1 + beta1[c];  // const bias

        // GEMM1 B fragment pairs: features k = [x,y | z,r | 1,xc | yc,zm]
        const __half2 q0 = __floats2half2_rn(ax,  ay);
        const __half2 q1 = __floats2half2_rn(az,  ar);
        const __half2 q2 = __floats2half2_rn(k7, -k4);
        const __half2 q3 = __floats2half2_rn(-k5, -k6);
        d_B1u[c*4 + 0] = *(const uint32_t*)&q0;
        d_B1u[c*4 + 1] = *(const uint32_t*)&q1;
        d_B1u[c*4 + 2] = *(const uint32_t*)&q2;
        d_B1u[c*4 + 3] = *(const uint32_t*)&q3;

        float s2 = g2[c] * rsqrtf(v2[c] + EPS_);
        for (int k = 0; k < 64; k++)
            d_Bh[c*64 + k] = __float2half(W2[k*64 + c] * s2);   // [n=c][k]
        d_t2f[c] = (b2[c] - m2[c]) * s2 + beta2[c];
    } else if (t == 64) {
        int f = 1;
        #pragma unroll 1
        for (int i = 1; i < nwords; i += 2) {
            if (npts_i32[i] != 0) { f = 0; break; }
        }
        d_i64flag = f;
    }
}

// ---------------- main kernel: 1 warp = 8 pillars, 4 warps/CTA ----------------
// SMEM: B tile only (64 rows x 144B = 9216)
#define ROWB     144
#define SMEM_TOT 9216

__global__ void __launch_bounds__(128, 3) pfn_mma(
    const float4* __restrict__ pillars,
    const void*  __restrict__ coords_raw,
    const void*  __restrict__ npts_raw,
    float* __restrict__ out, int P)
{
    extern __shared__ __align__(128) unsigned char smem[];
    const int tid  = threadIdx.x;
    const int wid  = tid >> 5;
    const int lane = tid & 31;

    // ---- B2 tile -> smem, then fragments -> registers (once per warp) ----
    {
        const uint4* gh = (const uint4*)d_Bh;   // 64 rows x 8 uint4
        #pragma unroll
        for (int g = tid; g < 512; g += 128) {
            const int row = g >> 3, c = g & 7;
            *(uint4*)(smem + row*ROWB + c*16) = gh[g];
        }
    }
    __syncthreads();

    const uint32_t boff = ((((lane >> 4) & 1) * 8 + (lane & 7)) * ROWB)
                        + ((lane >> 3) & 1) * 16;
    const uint32_t baseB = smem_u32(smem) + boff;
    uint32_t Bf[4][4][4];   // [np][kt][r]
    #pragma unroll
    for (int np = 0; np < 4; np++)
        #pragma unroll
        for (int kt = 0; kt < 4; kt++)
            ldsm4(baseB + np * 16 * ROWB + kt * 32,
                  Bf[np][kt][0], Bf[np][kt][1], Bf[np][kt][2], Bf[np][kt][3]);

    // ---- GEMM1 B fragments (1 reg per n-tile) ----
    const int q = lane & 3;
    uint32_t B1f[8];
    #pragma unroll
    for (int nt = 0; nt < 8; nt++)
        B1f[nt] = d_B1u[(nt*8 + (lane >> 2))*4 + q];

    const int i64 = d_i64flag;
    const int pfirst = (blockIdx.x * 4 + wid) * G_PIL;

    // ---- prefetch pillar 0 ----
    int npts_n = 0; float crow_n = 0.f, ccol_n = 0.f;
    float4 pt_n = make_float4(0.f, 0.f, 0.f, 0.f);
    if (pfirst < P) {
        if (i64) {
            npts_n = (int)((const long long*)npts_raw)[pfirst];
            crow_n = (float)((const long long*)coords_raw)[pfirst*2 + 0];
            ccol_n = (float)((const long long*)coords_raw)[pfirst*2 + 1];
        } else {
            npts_n = ((const int*)npts_raw)[pfirst];
            crow_n = (float)((const int*)coords_raw)[pfirst*2 + 0];
            ccol_n = (float)((const int*)coords_raw)[pfirst*2 + 1];
        }
        npts_n = min(max(npts_n, 0), 32);
        pt_n = pillars[pfirst * 32 + lane];
    }

    #pragma unroll 1
    for (int g = 0; g < G_PIL; g++) {
        const int p = pfirst + g;
        if (p >= P) break;

        const int npts = npts_n;
        const float crow = crow_n, ccol = ccol_n;
        const float4 pt = pt_n;

        // prefetch next pillar
        const int pn = p + 1;
        if (g + 1 < G_PIL && pn < P) {
            if (i64) {
                npts_n = (int)((const long long*)npts_raw)[pn];
                crow_n = (float)((const long long*)coords_raw)[pn*2 + 0];
                ccol_n = (float)((const long long*)coords_raw)[pn*2 + 1];
            } else {
                npts_n = ((const int*)npts_raw)[pn];
                crow_n = (float)((const int*)coords_raw)[pn*2 + 0];
                ccol_n = (float)((const int*)coords_raw)[pn*2 + 1];
            }
            npts_n = min(max(npts_n, 0), 32);
            pt_n = pillars[pn * 32 + lane];
        }

        if (npts == 0) {
            out[p*64 + lane]      = NEG_;
            out[p*64 + lane + 32] = NEG_;
            continue;
        }

        // masked z mean
        float zs = (lane < npts) ? pt.z : 0.0f;
        #pragma unroll
        for (int o = 16; o; o >>= 1) zs += __shfl_xor_sync(0xFFFFFFFFu, zs, o);
        const float zm = zs / fmaxf((float)npts, 1.0f);

        const float xc = (ccol + 0.5f) * RES_ + XMIN_;
        const float yc = (crow + 0.5f) * RES_ + YMIN_;

        float run[16];
        #pragma unroll
        for (int i = 0; i < 16; i++) run[i] = NEG_;

        const int nmt = (npts > 16) ? 2 : 1;
        #pragma unroll 1
        for (int mt = 0; mt < nmt; mt++) {
            // ---- GEMM1 A fragments: features of points (rows) this lane needs ----
            const int src0 = mt * 16 + (lane >> 2);
            const int src1 = src0 + 8;
            const float s0x = __shfl_sync(0xFFFFFFFFu, pt.x, src0);
            const float s0y = __shfl_sync(0xFFFFFFFFu, pt.y, src0);
            const float s0z = __shfl_sync(0xFFFFFFFFu, pt.z, src0);
            const float s0w = __shfl_sync(0xFFFFFFFFu, pt.w, src0);
            const float s1x = __shfl_sync(0xFFFFFFFFu, pt.x, src1);
            const float s1y = __shfl_sync(0xFFFFFFFFu, pt.y, src1);
            const float s1z = __shfl_sync(0xFFFFFFFFu, pt.z, src1);
            const float s1w = __shfl_sync(0xFFFFFFFFu, pt.w, src1);

            const float f00 = (q == 0) ? s0x : (q == 1) ? s0z : (q == 2) ? 1.0f : yc;
            const float f01 = (q == 0) ? s0y : (q == 1) ? s0w : (q == 2) ? xc  : zm;
            const float f10 = (q == 0) ? s1x : (q == 1) ? s1z : (q == 2) ? 1.0f : yc;
            const float f11 = (q == 0) ? s1y : (q == 1) ? s1w : (q == 2) ? xc  : zm;
            const uint32_t a1r0 = pkh2(f00, f01);
            const uint32_t a1r1 = pkh2(f10, f11);

            float D2[8][4];
            #pragma unroll
            for (int i = 0; i < 8; i++)
                #pragma unroll
                for (int w = 0; w < 4; w++) D2[i][w] = 0.0f;

            #pragma unroll
            for (int kt = 0; kt < 4; kt++) {
                // GEMM1 for the two n-tiles feeding this kt's A2 fragment
                float D1[2][4] = {{0.f,0.f,0.f,0.f},{0.f,0.f,0.f,0.f}};
                mma1688(D1[0], a1r0, a1r1, B1f[2*kt + 0]);
                mma1688(D1[1], a1r0, a1r1, B1f[2*kt + 1]);

                // relu + pack: D1 layout == A2 fragment layout
                const uint32_t a0 = pkh2(fmaxf(D1[0][0], 0.f), fmaxf(D1[0][1], 0.f));
                const uint32_t a1 = pkh2(fmaxf(D1[0][2], 0.f), fmaxf(D1[0][3], 0.f));
                const uint32_t a2 = pkh2(fmaxf(D1[1][0], 0.f), fmaxf(D1[1][1], 0.f));
                const uint32_t a3 = pkh2(fmaxf(D1[1][2], 0.f), fmaxf(D1[1][3], 0.f));

                #pragma unroll
                for (int np = 0; np < 4; np++) {
                    mma16816(D2[2*np+0], a0, a1, a2, a3, Bf[np][kt][0], Bf[np][kt][1]);
                    mma16816(D2[2*np+1], a0, a1, a2, a3, Bf[np][kt][2], Bf[np][kt][3]);
                }
            }

            // mask invalid rows, fold into running maxes
            const int rlo = mt * 16 + (lane >> 2);
            const bool v0 = (rlo < npts);
            const bool v2 = (rlo + 8 < npts);
            #pragma unroll
            for (int nt = 0; nt < 8; nt++) {
                const float e0 = v0 ? D2[nt][0] : NEG_;
                const float e1 = v0 ? D2[nt][1] : NEG_;
                const float e2 = v2 ? D2[nt][2] : NEG_;
                const float e3 = v2 ? D2[nt][3] : NEG_;
                run[2*nt+0] = fmaxf(run[2*nt+0], fmaxf(e0, e2));
                run[2*nt+1] = fmaxf(run[2*nt+1], fmaxf(e1, e3));
            }
        }

        // cross-lane max over the 8 row-groups
        #pragma unroll
        for (int i = 0; i < 16; i++) {
            run[i] = fmaxf(run[i], __shfl_xor_sync(0xFFFFFFFFu, run[i], 4));
            run[i] = fmaxf(run[i], __shfl_xor_sync(0xFFFFFFFFu, run[i], 8));
            run[i] = fmaxf(run[i], __shfl_xor_sync(0xFFFFFFFFu, run[i], 16));
        }

        if (lane < 4) {
            #pragma unroll
            for (int nt = 0; nt < 8; nt++) {
                const int col = nt * 8 + q * 2;
                const float2 t2 = *(const float2*)(d_t2f + col);
                float2 o;
                o.x = fmaxf(run[2*nt+0] + t2.x, 0.0f);
                o.y = fmaxf(run[2*nt+1] + t2.y, 0.0f);
                *(float2*)(out + p * 64 + col) = o;
            }
        }
    }
}

extern "C" void kernel_launch(void* const* d_in, const int* in_sizes, int n_in,
                              void* d_out, int out_size) {
    const float* pillars = (const float*)d_in[0];   // (P,32,4) f32
    const void*  coords  = d_in[1];                 // (P,2) int32 or int64
    const void*  npts    = d_in[2];                 // (P,)  int32 or int64
    const float* W1    = (const float*)d_in[3];
    const float* b1    = (const float*)d_in[4];
    const float* g1    = (const float*)d_in[5];
    const float* beta1 = (const float*)d_in[6];
    const float* m1    = (const float*)d_in[7];
    const float* v1    = (const float*)d_in[8];
    const float* W2    = (const float*)d_in[9];
    const float* b2    = (const float*)d_in[10];
    const float* g2    = (const float*)d_in[11];
    const float* beta2 = (const float*)d_in[12];
    const float* m2    = (const float*)d_in[13];
    const float* v2    = (const float*)d_in[14];

    const int P = in_sizes[2];

    const int nwords = (P >= 64) ? 129 : (2 * P);
    pfn_prep<<<1, 128>>>(W1, b1, g1, beta1, m1, v1, W2, b2, g2, beta2, m2, v2,
                         (const int*)npts, nwords);

    const int blocks = (P + 4 * G_PIL - 1) / (4 * G_PIL);
    pfn_mma<<<blocks, 128, SMEM_TOT>>>(
        (const float4*)pillars, coords, npts, (float*)d_out, P);
}

// round 16
// speedup vs baseline: 7.5530x; 1.1012x over previous
#include <cuda_runtime.h>
#include <cuda_fp16.h>
#include <cstdint>

#define RES_   0.16f
#define XMIN_ (-51.2f)
#define YMIN_ (-51.2f)
#define EPS_   1e-5f
#define NEG_  (-1000000000.0f)
#define NEGH_ (-60000.0f)
#define G_PIL  8

// Folded params (device globals: allocation-free).
__device__ __align__(8) float d_t2f[64];
__device__ __align__(16) __half d_Bh[64 * 64];    // [n][k] = fp16(W2f[k][n])
__device__ __align__(16) uint32_t d_B1u[64 * 4];  // [n][q] = half2 B1 frag pairs
__device__ int d_i64flag;

__device__ __forceinline__ uint32_t smem_u32(const void* p) {
    uint32_t a;
    asm("{ .reg .u64 t; cvta.to.shared.u64 t, %1; cvt.u32.u64 %0, t; }" : "=r"(a) : "l"(p));
    return a;
}
__device__ __forceinline__ void ldsm4(uint32_t a, uint32_t& r0, uint32_t& r1,
                                      uint32_t& r2, uint32_t& r3) {
    asm volatile("ldmatrix.sync.aligned.m8n8.x4.shared.b16 {%0,%1,%2,%3}, [%4];"
                 : "=r"(r0), "=r"(r1), "=r"(r2), "=r"(r3) : "r"(a));
}
__device__ __forceinline__ void mma16816(float* d, uint32_t a0, uint32_t a1,
                                         uint32_t a2, uint32_t a3,
                                         uint32_t b0, uint32_t b1) {
    asm volatile(
        "mma.sync.aligned.m16n8k16.row.col.f32.f16.f16.f32 "
        "{%0,%1,%2,%3}, {%4,%5,%6,%7}, {%8,%9}, {%0,%1,%2,%3};"
        : "+f"(d[0]), "+f"(d[1]), "+f"(d[2]), "+f"(d[3])
        : "r"(a0), "r"(a1), "r"(a2), "r"(a3), "r"(b0), "r"(b1));
}
__device__ __forceinline__ void mma1688(float* d, uint32_t a0, uint32_t a1,
                                        uint32_t b0) {
    asm volatile(
        "mma.sync.aligned.m16n8k8.row.col.f32.f16.f16.f32 "
        "{%0,%1,%2,%3}, {%4,%5}, {%6}, {%0,%1,%2,%3};"
        : "+f"(d[0]), "+f"(d[1]), "+f"(d[2]), "+f"(d[3])
        : "r"(a0), "r"(a1), "r"(b0));
}
__device__ __forceinline__ uint32_t pkh2(float lo, float hi) {
    const __half2 h = __floats2half2_rn(lo, hi);
    return *(const uint32_t*)&h;
}
__device__ __forceinline__ uint32_t hmax2u(uint32_t a, uint32_t b) {
    const __half2 r = __hmax2(*(const __half2*)&a, *(const __half2*)&b);
    return *(const uint32_t*)&r;
}

// prep (lanes 0-63) + int-width detect (lane 64), one launch
__global__ void pfn_prep(const float* __restrict__ W1, const float* __restrict__ b1,
                         const float* __restrict__ g1, const float* __restrict__ beta1,
                         const float* __restrict__ m1, const float* __restrict__ v1,
                         const float* __restrict__ W2, const float* __restrict__ b2,
                         const float* __restrict__ g2, const float* __restrict__ beta2,
                         const float* __restrict__ m2, const float* __restrict__ v2,
                         const int* __restrict__ npts_i32, int nwords) {
    const int t = threadIdx.x;
    if (t < 64) {
        const int c = t;
        float s1 = g1[c] * rsqrtf(v1[c] + EPS_);
        float w0 = W1[0*64+c], w1 = W1[1*64+c], w2 = W1[2*64+c];
        float w3 = W1[3*64+c], w4 = W1[4*64+c], w5 = W1[5*64+c];
        float w6 = W1[6*64+c], w7 = W1[7*64+c], w8 = W1[8*64+c];
        const float ax = (w0 + w4 + w7) * s1;       // x
        const float ay = (w1 + w5 + w8) * s1;       // y
        const float az = (w2 + w6) * s1;            // z
        const float ar = w3 * s1;                   // r
        const float k4 = (w4 + w7) * s1;            // xc coeff
        const float k5 = (w5 + w8) * s1;            // yc coeff
        const float k6 = w6 * s1;                   // zm coeff
        const float k7 = (b1[c] - m1[c]) * s1 + beta1[c];  // const bias

        // GEMM1 B fragment pairs: features k = [x,y | z,r | 1,xc | yc,zm]
        d_B1u[c*4 + 0] = pkh2(ax,  ay);
        d_B1u[c*4 + 1] = pkh2(az,  ar);
        d_B1u[c*4 + 2] = pkh2(k7, -k4);
        d_B1u[c*4 + 3] = pkh2(-k5, -k6);

        float s2 = g2[c] * rsqrtf(v2[c] + EPS_);
        for (int k = 0; k < 64; k++)
            d_Bh[c*64 + k] = __float2half(W2[k*64 + c] * s2);   // [n=c][k]
        d_t2f[c] = (b2[c] - m2[c]) * s2 + beta2[c];
    } else if (t == 64) {
        int f = 1;
        #pragma unroll 1
        for (int i = 1; i < nwords; i += 2) {
            if (npts_i32[i] != 0) { f = 0; break; }
        }
        d_i64flag = f;
    }
}

// ---------------- main kernel: 1 warp = 8 pillars, 4 warps/CTA ----------------
// SMEM: B tile only (64 rows x 144B = 9216)
#define ROWB     144
#define SMEM_TOT 9216

__global__ void __launch_bounds__(128, 3) pfn_mma(
    const float4* __restrict__ pillars,
    const void*  __restrict__ coords_raw,
    const void*  __restrict__ npts_raw,
    float* __restrict__ out, int P)
{
    extern __shared__ __align__(128) unsigned char smem[];
    const int tid  = threadIdx.x;
    const int wid  = tid >> 5;
    const int lane = tid & 31;

    // ---- B2 tile -> smem, then fragments -> registers (once per warp) ----
    {
        const uint4* gh = (const uint4*)d_Bh;   // 64 rows x 8 uint4
        #pragma unroll
        for (int g = tid; g < 512; g += 128) {
            const int row = g >> 3, c = g & 7;
            *(uint4*)(smem + row*ROWB + c*16) = gh[g];
        }
    }
    __syncthreads();

    const uint32_t boff = ((((lane >> 4) & 1) * 8 + (lane & 7)) * ROWB)
                        + ((lane >> 3) & 1) * 16;
    const uint32_t baseB = smem_u32(smem) + boff;
    uint32_t Bf[4][4][4];   // [np][kt][r]
    #pragma unroll
    for (int np = 0; np < 4; np++)
        #pragma unroll
        for (int kt = 0; kt < 4; kt++)
            ldsm4(baseB + np * 16 * ROWB + kt * 32,
                  Bf[np][kt][0], Bf[np][kt][1], Bf[np][kt][2], Bf[np][kt][3]);

    // ---- GEMM1 B fragments (1 reg per n-tile) ----
    const int q = lane & 3;
    uint32_t B1f[8];
    #pragma unroll
    for (int nt = 0; nt < 8; nt++)
        B1f[nt] = d_B1u[(nt*8 + (lane >> 2))*4 + q];

    const uint32_t neg2 = pkh2(NEGH_, NEGH_);
    const int i64 = d_i64flag;
    const int pfirst = (blockIdx.x * 4 + wid) * G_PIL;

    // ---- prefetch pillar 0 ----
    int npts_n = 0; float crow_n = 0.f, ccol_n = 0.f;
    float4 pt_n = make_float4(0.f, 0.f, 0.f, 0.f);
    if (pfirst < P) {
        if (i64) {
            npts_n = (int)((const long long*)npts_raw)[pfirst];
            crow_n = (float)((const long long*)coords_raw)[pfirst*2 + 0];
            ccol_n = (float)((const long long*)coords_raw)[pfirst*2 + 1];
        } else {
            npts_n = ((const int*)npts_raw)[pfirst];
            crow_n = (float)((const int*)coords_raw)[pfirst*2 + 0];
            ccol_n = (float)((const int*)coords_raw)[pfirst*2 + 1];
        }
        npts_n = min(max(npts_n, 0), 32);
        pt_n = pillars[pfirst * 32 + lane];
    }

    #pragma unroll 1
    for (int g = 0; g < G_PIL; g++) {
        const int p = pfirst + g;
        if (p >= P) break;

        const int npts = npts_n;
        const float crow = crow_n, ccol = ccol_n;
        const float4 pt = pt_n;

        // prefetch next pillar
        const int pn = p + 1;
        if (g + 1 < G_PIL && pn < P) {
            if (i64) {
                npts_n = (int)((const long long*)npts_raw)[pn];
                crow_n = (float)((const long long*)coords_raw)[pn*2 + 0];
                ccol_n = (float)((const long long*)coords_raw)[pn*2 + 1];
            } else {
                npts_n = ((const int*)npts_raw)[pn];
                crow_n = (float)((const int*)coords_raw)[pn*2 + 0];
                ccol_n = (float)((const int*)coords_raw)[pn*2 + 1];
            }
            npts_n = min(max(npts_n, 0), 32);
            pt_n = pillars[pn * 32 + lane];
        }

        if (npts == 0) {
            out[p*64 + lane]      = NEG_;
            out[p*64 + lane + 32] = NEG_;
            continue;
        }

        // masked z mean
        float zs = (lane < npts) ? pt.z : 0.0f;
        #pragma unroll
        for (int o = 16; o; o >>= 1) zs += __shfl_xor_sync(0xFFFFFFFFu, zs, o);
        const float zm = zs / fmaxf((float)npts, 1.0f);

        const float xc = (ccol + 0.5f) * RES_ + XMIN_;
        const float yc = (crow + 0.5f) * RES_ + YMIN_;

        // packed feature words (per-lane point data + per-pillar constants)
        const uint32_t wxy = pkh2(pt.x, pt.y);
        const uint32_t wzr = pkh2(pt.z, pt.w);
        const uint32_t cw2 = pkh2(1.0f, xc);
        const uint32_t cw3 = pkh2(yc, zm);

        uint32_t run[8];
        #pragma unroll
        for (int i = 0; i < 8; i++) run[i] = neg2;

        const int nmt = (npts > 16) ? 2 : 1;
        #pragma unroll 1
        for (int mt = 0; mt < nmt; mt++) {
            // ---- GEMM1 A fragments via packed shuffles ----
            const int src0 = mt * 16 + (lane >> 2);
            const int src1 = src0 + 8;
            const uint32_t s0a = __shfl_sync(0xFFFFFFFFu, wxy, src0);
            const uint32_t s0b = __shfl_sync(0xFFFFFFFFu, wzr, src0);
            const uint32_t s1a = __shfl_sync(0xFFFFFFFFu, wxy, src1);
            const uint32_t s1b = __shfl_sync(0xFFFFFFFFu, wzr, src1);

            const uint32_t a1r0 = (q == 0) ? s0a : (q == 1) ? s0b : (q == 2) ? cw2 : cw3;
            const uint32_t a1r1 = (q == 0) ? s1a : (q == 1) ? s1b : (q == 2) ? cw2 : cw3;

            float D2[8][4];
            #pragma unroll
            for (int i = 0; i < 8; i++)
                #pragma unroll
                for (int w = 0; w < 4; w++) D2[i][w] = 0.0f;

            #pragma unroll
            for (int kt = 0; kt < 4; kt++) {
                // GEMM1 for the two n-tiles feeding this kt's A2 fragment
                float D1[2][4] = {{0.f,0.f,0.f,0.f},{0.f,0.f,0.f,0.f}};
                mma1688(D1[0], a1r0, a1r1, B1f[2*kt + 0]);
                mma1688(D1[1], a1r0, a1r1, B1f[2*kt + 1]);

                // relu + pack: D1 layout == A2 fragment layout
                const uint32_t a0 = pkh2(fmaxf(D1[0][0], 0.f), fmaxf(D1[0][1], 0.f));
                const uint32_t a1 = pkh2(fmaxf(D1[0][2], 0.f), fmaxf(D1[0][3], 0.f));
                const uint32_t a2 = pkh2(fmaxf(D1[1][0], 0.f), fmaxf(D1[1][1], 0.f));
                const uint32_t a3 = pkh2(fmaxf(D1[1][2], 0.f), fmaxf(D1[1][3], 0.f));

                #pragma unroll
                for (int np = 0; np < 4; np++) {
                    mma16816(D2[2*np+0], a0, a1, a2, a3, Bf[np][kt][0], Bf[np][kt][1]);
                    mma16816(D2[2*np+1], a0, a1, a2, a3, Bf[np][kt][2], Bf[np][kt][3]);
                }
            }

            // mask invalid rows (packed) and fold into packed running maxes
            const int rlo = mt * 16 + (lane >> 2);
            const bool v0 = (rlo < npts);
            const bool v2 = (rlo + 8 < npts);
            #pragma unroll
            for (int nt = 0; nt < 8; nt++) {
                uint32_t lo = pkh2(D2[nt][0], D2[nt][1]);   // rows rlo
                uint32_t hi = pkh2(D2[nt][2], D2[nt][3]);   // rows rlo+8
                lo = v0 ? lo : neg2;
                hi = v2 ? hi : neg2;
                run[nt] = hmax2u(run[nt], hmax2u(lo, hi));
            }
        }

        // cross-lane packed max over the 8 row-groups
        #pragma unroll
        for (int i = 0; i < 8; i++) {
            run[i] = hmax2u(run[i], __shfl_xor_sync(0xFFFFFFFFu, run[i], 4));
            run[i] = hmax2u(run[i], __shfl_xor_sync(0xFFFFFFFFu, run[i], 8));
            run[i] = hmax2u(run[i], __shfl_xor_sync(0xFFFFFFFFu, run[i], 16));
        }

        if (lane < 4) {
            #pragma unroll
            for (int nt = 0; nt < 8; nt++) {
                const int col = nt * 8 + q * 2;
                const float2 t2 = *(const float2*)(d_t2f + col);
                const __half2 rv = *(const __half2*)&run[nt];
                float2 o;
                o.x = fmaxf(__low2float(rv)  + t2.x, 0.0f);
                o.y = fmaxf(__high2float(rv) + t2.y, 0.0f);
                *(float2*)(out + p * 64 + col) = o;
            }
        }
    }
}

extern "C" void kernel_launch(void* const* d_in, const int* in_sizes, int n_in,
                              void* d_out, int out_size) {
    const float* pillars = (const float*)d_in[0];   // (P,32,4) f32
    const void*  coords  = d_in[1];                 // (P,2) int32 or int64
    const void*  npts    = d_in[2];                 // (P,)  int32 or int64
    const float* W1    = (const float*)d_in[3];
    const float* b1    = (const float*)d_in[4];
    const float* g1    = (const float*)d_in[5];
    const float* beta1 = (const float*)d_in[6];
    const float* m1    = (const float*)d_in[7];
    const float* v1    = (const float*)d_in[8];
    const float* W2    = (const float*)d_in[9];
    const float* b2    = (const float*)d_in[10];
    const float* g2    = (const float*)d_in[11];
    const float* beta2 = (const float*)d_in[12];
    const float* m2    = (const float*)d_in[13];
    const float* v2    = (const float*)d_in[14];

    const int P = in_sizes[2];

    const int nwords = (P >= 64) ? 129 : (2 * P);
    pfn_prep<<<1, 128>>>(W1, b1, g1, beta1, m1, v1, W2, b2, g2, beta2, m2, v2,
                         (const int*)npts, nwords);

    const int blocks = (P + 4 * G_PIL - 1) / (4 * G_PIL);
    pfn_mma<<<blocks, 128, SMEM_TOT>>>(
        (const float4*)pillars, coords, npts, (float*)d_out, P);
}

// round 17
// speedup vs baseline: 7.7902x; 1.0314x over previous
#include <cuda_runtime.h>
#include <cuda_fp16.h>
#include <cstdint>

#define RES_   0.16f
#define XMIN_ (-51.2f)
#define YMIN_ (-51.2f)
#define EPS_   1e-5f
#define NEG_  (-1000000000.0f)
#define NEGH_ (-60000.0f)
#define G_PIL  8

// Folded params (device globals: allocation-free).
__device__ __align__(8) float d_t2f[64];
__device__ __align__(16) __half d_Bh[64 * 64];    // [n][k] = fp16(W2f[k][n])
__device__ __align__(16) uint32_t d_B1u[64 * 4];  // [n][q] = half2 B1 frag pairs
__device__ int d_i64flag;

__device__ __forceinline__ uint32_t smem_u32(const void* p) {
    uint32_t a;
    asm("{ .reg .u64 t; cvta.to.shared.u64 t, %1; cvt.u32.u64 %0, t; }" : "=r"(a) : "l"(p));
    return a;
}
__device__ __forceinline__ void ldsm4(uint32_t a, uint32_t& r0, uint32_t& r1,
                                      uint32_t& r2, uint32_t& r3) {
    asm volatile("ldmatrix.sync.aligned.m8n8.x4.shared.b16 {%0,%1,%2,%3}, [%4];"
                 : "=r"(r0), "=r"(r1), "=r"(r2), "=r"(r3) : "r"(a));
}
// GEMM2: f16 accumulate, D/C = 2 packed-half2 regs
__device__ __forceinline__ void mma16816h(uint32_t* d, uint32_t a0, uint32_t a1,
                                          uint32_t a2, uint32_t a3,
                                          uint32_t b0, uint32_t b1) {
    asm volatile(
        "mma.sync.aligned.m16n8k16.row.col.f16.f16.f16.f16 "
        "{%0,%1}, {%2,%3,%4,%5}, {%6,%7}, {%0,%1};"
        : "+r"(d[0]), "+r"(d[1])
        : "r"(a0), "r"(a1), "r"(a2), "r"(a3), "r"(b0), "r"(b1));
}
// GEMM1: f16 accumulate, D = 2 packed-half2 regs (C = 0)
__device__ __forceinline__ void mma1688h(uint32_t* d, uint32_t a0, uint32_t a1,
                                         uint32_t b0) {
    asm volatile(
        "mma.sync.aligned.m16n8k8.row.col.f16.f16.f16.f16 "
        "{%0,%1}, {%2,%3}, {%4}, {%5,%5};"
        : "=r"(d[0]), "=r"(d[1])
        : "r"(a0), "r"(a1), "r"(b0), "r"(0u));
}
__device__ __forceinline__ uint32_t pkh2(float lo, float hi) {
    const __half2 h = __floats2half2_rn(lo, hi);
    return *(const uint32_t*)&h;
}
__device__ __forceinline__ uint32_t hmax2u(uint32_t a, uint32_t b) {
    const __half2 r = __hmax2(*(const __half2*)&a, *(const __half2*)&b);
    return *(const uint32_t*)&r;
}

// prep (lanes 0-63) + int-width detect (lane 64), one launch
__global__ void pfn_prep(const float* __restrict__ W1, const float* __restrict__ b1,
                         const float* __restrict__ g1, const float* __restrict__ beta1,
                         const float* __restrict__ m1, const float* __restrict__ v1,
                         const float* __restrict__ W2, const float* __restrict__ b2,
                         const float* __restrict__ g2, const float* __restrict__ beta2,
                         const float* __restrict__ m2, const float* __restrict__ v2,
                         const int* __restrict__ npts_i32, int nwords) {
    const int t = threadIdx.x;
    if (t < 64) {
        const int c = t;
        float s1 = g1[c] * rsqrtf(v1[c] + EPS_);
        float w0 = W1[0*64+c], w1 = W1[1*64+c], w2 = W1[2*64+c];
        float w3 = W1[3*64+c], w4 = W1[4*64+c], w5 = W1[5*64+c];
        float w6 = W1[6*64+c], w7 = W1[7*64+c], w8 = W1[8*64+c];
        const float ax = (w0 + w4 + w7) * s1;       // x
        const float ay = (w1 + w5 + w8) * s1;       // y
        const float az = (w2 + w6) * s1;            // z
        const float ar = w3 * s1;                   // r
        const float k4 = (w4 + w7) * s1;            // xc coeff
        const float k5 = (w5 + w8) * s1;            // yc coeff
        const float k6 = w6 * s1;                   // zm coeff
        const float k7 = (b1[c] - m1[c]) * s1 + beta1[c];  // const bias

        // GEMM1 B fragment pairs: features k = [x,y | z,r | 1,xc | yc,zm]
        d_B1u[c*4 + 0] = pkh2(ax,  ay);
        d_B1u[c*4 + 1] = pkh2(az,  ar);
        d_B1u[c*4 + 2] = pkh2(k7, -k4);
        d_B1u[c*4 + 3] = pkh2(-k5, -k6);

        float s2 = g2[c] * rsqrtf(v2[c] + EPS_);
        for (int k = 0; k < 64; k++)
            d_Bh[c*64 + k] = __float2half(W2[k*64 + c] * s2);   // [n=c][k]
        d_t2f[c] = (b2[c] - m2[c]) * s2 + beta2[c];
    } else if (t == 64) {
        int f = 1;
        #pragma unroll 1
        for (int i = 1; i < nwords; i += 2) {
            if (npts_i32[i] != 0) { f = 0; break; }
        }
        d_i64flag = f;
    }
}

// ---------------- main kernel: 1 warp = 8 pillars, 4 warps/CTA ----------------
// SMEM: B tile only (64 rows x 144B = 9216)
#define ROWB     144
#define SMEM_TOT 9216

__global__ void __launch_bounds__(128, 3) pfn_mma(
    const float4* __restrict__ pillars,
    const void*  __restrict__ coords_raw,
    const void*  __restrict__ npts_raw,
    float* __restrict__ out, int P)
{
    extern __shared__ __align__(128) unsigned char smem[];
    const int tid  = threadIdx.x;
    const int wid  = tid >> 5;
    const int lane = tid & 31;

    // ---- B2 tile -> smem, then fragments -> registers (once per warp) ----
    {
        const uint4* gh = (const uint4*)d_Bh;   // 64 rows x 8 uint4
        #pragma unroll
        for (int g = tid; g < 512; g += 128) {
            const int row = g >> 3, c = g & 7;
            *(uint4*)(smem + row*ROWB + c*16) = gh[g];
        }
    }
    __syncthreads();

    const uint32_t boff = ((((lane >> 4) & 1) * 8 + (lane & 7)) * ROWB)
                        + ((lane >> 3) & 1) * 16;
    const uint32_t baseB = smem_u32(smem) + boff;
    uint32_t Bf[4][4][4];   // [np][kt][r]
    #pragma unroll
    for (int np = 0; np < 4; np++)
        #pragma unroll
        for (int kt = 0; kt < 4; kt++)
            ldsm4(baseB + np * 16 * ROWB + kt * 32,
                  Bf[np][kt][0], Bf[np][kt][1], Bf[np][kt][2], Bf[np][kt][3]);

    // ---- GEMM1 B fragments (1 reg per n-tile) ----
    const int q = lane & 3;
    uint32_t B1f[8];
    #pragma unroll
    for (int nt = 0; nt < 8; nt++)
        B1f[nt] = d_B1u[(nt*8 + (lane >> 2))*4 + q];

    const uint32_t neg2 = pkh2(NEGH_, NEGH_);
    const int i64 = d_i64flag;
    const int pfirst = (blockIdx.x * 4 + wid) * G_PIL;

    // ---- prefetch pillar 0 ----
    int npts_n = 0; float crow_n = 0.f, ccol_n = 0.f;
    float4 pt_n = make_float4(0.f, 0.f, 0.f, 0.f);
    if (pfirst < P) {
        if (i64) {
            npts_n = (int)((const long long*)npts_raw)[pfirst];
            crow_n = (float)((const long long*)coords_raw)[pfirst*2 + 0];
            ccol_n = (float)((const long long*)coords_raw)[pfirst*2 + 1];
        } else {
            npts_n = ((const int*)npts_raw)[pfirst];
            crow_n = (float)((const int*)coords_raw)[pfirst*2 + 0];
            ccol_n = (float)((const int*)coords_raw)[pfirst*2 + 1];
        }
        npts_n = min(max(npts_n, 0), 32);
        pt_n = pillars[pfirst * 32 + lane];
    }

    #pragma unroll 1
    for (int g = 0; g < G_PIL; g++) {
        const int p = pfirst + g;
        if (p >= P) break;

        const int npts = npts_n;
        const float crow = crow_n, ccol = ccol_n;
        const float4 pt = pt_n;

        // prefetch next pillar
        const int pn = p + 1;
        if (g + 1 < G_PIL && pn < P) {
            if (i64) {
                npts_n = (int)((const long long*)npts_raw)[pn];
                crow_n = (float)((const long long*)coords_raw)[pn*2 + 0];
                ccol_n = (float)((const long long*)coords_raw)[pn*2 + 1];
            } else {
                npts_n = ((const int*)npts_raw)[pn];
                crow_n = (float)((const int*)coords_raw)[pn*2 + 0];
                ccol_n = (float)((const int*)coords_raw)[pn*2 + 1];
            }
            npts_n = min(max(npts_n, 0), 32);
            pt_n = pillars[pn * 32 + lane];
        }

        if (npts == 0) {
            out[p*64 + lane]      = NEG_;
            out[p*64 + lane + 32] = NEG_;
            continue;
        }

        // masked z mean
        float zs = (lane < npts) ? pt.z : 0.0f;
        #pragma unroll
        for (int o = 16; o; o >>= 1) zs += __shfl_xor_sync(0xFFFFFFFFu, zs, o);
        const float zm = zs / fmaxf((float)npts, 1.0f);

        const float xc = (ccol + 0.5f) * RES_ + XMIN_;
        const float yc = (crow + 0.5f) * RES_ + YMIN_;

        // packed feature words (per-lane point data + per-pillar constants)
        const uint32_t wxy = pkh2(pt.x, pt.y);
        const uint32_t wzr = pkh2(pt.z, pt.w);
        const uint32_t cw2 = pkh2(1.0f, xc);
        const uint32_t cw3 = pkh2(yc, zm);

        uint32_t run[8];
        #pragma unroll
        for (int i = 0; i < 8; i++) run[i] = neg2;

        const int nmt = (npts > 16) ? 2 : 1;
        #pragma unroll 1
        for (int mt = 0; mt < nmt; mt++) {
            // ---- GEMM1 A fragments via packed shuffles ----
            const int src0 = mt * 16 + (lane >> 2);
            const int src1 = src0 + 8;
            const uint32_t s0a = __shfl_sync(0xFFFFFFFFu, wxy, src0);
            const uint32_t s0b = __shfl_sync(0xFFFFFFFFu, wzr, src0);
            const uint32_t s1a = __shfl_sync(0xFFFFFFFFu, wxy, src1);
            const uint32_t s1b = __shfl_sync(0xFFFFFFFFu, wzr, src1);

            const uint32_t a1r0 = (q == 0) ? s0a : (q == 1) ? s0b : (q == 2) ? cw2 : cw3;
            const uint32_t a1r1 = (q == 0) ? s1a : (q == 1) ? s1b : (q == 2) ? cw2 : cw3;

            uint32_t D2[8][2];
            #pragma unroll
            for (int i = 0; i < 8; i++) { D2[i][0] = 0u; D2[i][1] = 0u; }

            #pragma unroll
            for (int kt = 0; kt < 4; kt++) {
                // GEMM1 (f16 acc): D layout == A2 fragment layout, no packing
                uint32_t D1a[2], D1b[2];
                mma1688h(D1a, a1r0, a1r1, B1f[2*kt + 0]);
                mma1688h(D1b, a1r0, a1r1, B1f[2*kt + 1]);

                // relu in packed fp16
                const uint32_t a0 = hmax2u(D1a[0], 0u);
                const uint32_t a1 = hmax2u(D1a[1], 0u);
                const uint32_t a2 = hmax2u(D1b[0], 0u);
                const uint32_t a3 = hmax2u(D1b[1], 0u);

                #pragma unroll
                for (int np = 0; np < 4; np++) {
                    mma16816h(D2[2*np+0], a0, a1, a2, a3, Bf[np][kt][0], Bf[np][kt][1]);
                    mma16816h(D2[2*np+1], a0, a1, a2, a3, Bf[np][kt][2], Bf[np][kt][3]);
                }
            }

            // mask invalid rows (packed) and fold into packed running maxes
            const int rlo = mt * 16 + (lane >> 2);
            const bool v0 = (rlo < npts);
            const bool v2 = (rlo + 8 < npts);
            #pragma unroll
            for (int nt = 0; nt < 8; nt++) {
                const uint32_t lo = v0 ? D2[nt][0] : neg2;   // rows rlo
                const uint32_t hi = v2 ? D2[nt][1] : neg2;   // rows rlo+8
                run[nt] = hmax2u(run[nt], hmax2u(lo, hi));
            }
        }

        // cross-lane packed max over the 8 row-groups
        #pragma unroll
        for (int i = 0; i < 8; i++) {
            run[i] = hmax2u(run[i], __shfl_xor_sync(0xFFFFFFFFu, run[i], 4));
            run[i] = hmax2u(run[i], __shfl_xor_sync(0xFFFFFFFFu, run[i], 8));
            run[i] = hmax2u(run[i], __shfl_xor_sync(0xFFFFFFFFu, run[i], 16));
        }

        if (lane < 4) {
            #pragma unroll
            for (int nt = 0; nt < 8; nt++) {
                const int col = nt * 8 + q * 2;
                const float2 t2 = *(const float2*)(d_t2f + col);
                const __half2 rv = *(const __half2*)&run[nt];
                float2 o;
                o.x = fmaxf(__low2float(rv)  + t2.x, 0.0f);
                o.y = fmaxf(__high2float(rv) + t2.y, 0.0f);
                *(float2*)(out + p * 64 + col) = o;
            }
        }
    }
}

extern "C" void kernel_launch(void* const* d_in, const int* in_sizes, int n_in,
                              void* d_out, int out_size) {
    const float* pillars = (const float*)d_in[0];   // (P,32,4) f32
    const void*  coords  = d_in[1];                 // (P,2) int32 or int64
    const void*  npts    = d_in[2];                 // (P,)  int32 or int64
    const float* W1    = (const float*)d_in[3];
    const float* b1    = (const float*)d_in[4];
    const float* g1    = (const float*)d_in[5];
    const float* beta1 = (const float*)d_in[6];
    const float* m1    = (const float*)d_in[7];
    const float* v1    = (const float*)d_in[8];
    const float* W2    = (const float*)d_in[9];
    const float* b2    = (const float*)d_in[10];
    const float* g2    = (const float*)d_in[11];
    const float* beta2 = (const float*)d_in[12];
    const float* m2    = (const float*)d_in[13];
    const float* v2    = (const float*)d_in[14];

    const int P = in_sizes[2];

    const int nwords = (P >= 64) ? 129 : (2 * P);
    pfn_prep<<<1, 128>>>(W1, b1, g1, beta1, m1, v1, W2, b2, g2, beta2, m2, v2,
                         (const int*)npts, nwords);

    const int blocks = (P + 4 * G_PIL - 1) / (4 * G_PIL);
    pfn_mma<<<blocks, 128, SMEM_TOT>>>(
        (const float4*)pillars, coords, npts, (float*)d_out, P);
}